// round 13
// baseline (speedup 1.0000x reference)
#include <cuda_runtime.h>
#include <cuda_fp16.h>
#include <math.h>

// Problem constants (fixed shapes: B=2,S=2048,H=2048,E=8,A=64,NS=16384)
#define T_TOK   4096
#define H_DIM   2048
#define E_NUM   8
#define A_NUM   64
#define NS_NUM  16384
#define H_SHIFT 11
#define H_MASK  2047
#define PADMAX  4608
#define MAXBLK  1152

// GEMM: C[T,H] = fp16(x) @ fp16(W)^T, K = 2048, fp32 accumulate
#define KC      2048
#define BM      128
#define BN      256
#define BK      64
#define NCH     (KC / BK)            // 32
#define LDSB    144                  // smem row stride bytes (64 fp16 + 16 pad)
#define ABYTES  (BM * LDSB)          // 18432
#define STAGEB  ((BM + BN) * LDSB)   // 55296
#define NSTG    4
#define SMEM_MMA (NSTG * STAGEB)     // 221184

// ---------------- device scratch (no allocations allowed) ----------------
__device__ __half         g_xh[(size_t)T_TOK * KC];     // 16MB fp16(x)
__device__ __half         g_wh[(size_t)H_DIM * KC];     // 8MB  fp16(W)
__device__ float          g_contrib[(size_t)T_TOK * H_DIM];  // 32MB sparse contrib
__device__ float          g_weighted[E_NUM * NS_NUM];
__device__ float          g_wsrtT[(size_t)NS_NUM * E_NUM];   // entry-major: [pos][e]
__device__ unsigned short g_colsrt[NS_NUM];             // col per CSR entry
__device__ int            g_counts[H_DIM];
__device__ int            g_rowptr[H_DIM + 1];
__device__ int            g_offsets[H_DIM];
__device__ int            g_e0[T_TOK];
__device__ int            g_e1[T_TOK];
__device__ float          g_rw0[T_TOK];
__device__ float          g_rw1[T_TOK];
// pair grouping (4 tokens per block)
__device__ int            g_paircnt[64];
__device__ int            g_pairoff[64];
__device__ int            g_tokord[PADMAX];
__device__ int            g_blkpair[MAXBLK];
__device__ int            g_total_blocks;

// ---------------- static stream/event resources (created pre-checkpoint) ----------------
struct GraphForkResources {
    cudaStream_t side;
    cudaEvent_t  fork, join;
    GraphForkResources() {
        cudaStreamCreateWithFlags(&side, cudaStreamNonBlocking);
        cudaEventCreateWithFlags(&fork, cudaEventDisableTiming);
        cudaEventCreateWithFlags(&join, cudaEventDisableTiming);
    }
};
static GraphForkResources g_fork_res;

// ---------------- ptx helpers (compute_80-level, safe on compute_103) ----------------
__device__ __forceinline__ unsigned smem_u32(const void* p) {
    unsigned r;
    asm("{ .reg .u64 t; cvta.to.shared.u64 t, %1; cvt.u32.u64 %0, t; }" : "=r"(r) : "l"(p));
    return r;
}
__device__ __forceinline__ void cp16(unsigned dst, const void* src) {
    asm volatile("cp.async.cg.shared.global [%0], [%1], 16;\n" :: "r"(dst), "l"(src));
}
__device__ __forceinline__ void cp_commit() { asm volatile("cp.async.commit_group;\n" ::: "memory"); }
__device__ __forceinline__ void cp_wait2()  { asm volatile("cp.async.wait_group 2;\n" ::: "memory"); }
__device__ __forceinline__ void ldsm4(unsigned* r, unsigned addr) {
    asm volatile("ldmatrix.sync.aligned.m8n8.x4.shared.b16 {%0,%1,%2,%3}, [%4];"
                 : "=r"(r[0]), "=r"(r[1]), "=r"(r[2]), "=r"(r[3]) : "r"(addr));
}
__device__ __forceinline__ void mma16816(float* d, const unsigned* a, unsigned b0, unsigned b1) {
    asm volatile(
        "mma.sync.aligned.m16n8k16.row.col.f32.f16.f16.f32 "
        "{%0,%1,%2,%3}, {%4,%5,%6,%7}, {%8,%9}, {%0,%1,%2,%3};"
        : "+f"(d[0]), "+f"(d[1]), "+f"(d[2]), "+f"(d[3])
        : "r"(a[0]), "r"(a[1]), "r"(a[2]), "r"(a[3]), "r"(b0), "r"(b1));
}

// ---------------- fp16 conversion (x and W share row length 2048) ----------------
__global__ __launch_bounds__(256) void convert_fp16_kernel(
    const float* __restrict__ src, __half* __restrict__ dst)
{
    int idx2 = blockIdx.x * 256 + threadIdx.x;          // float2 index
    float2 v = *(const float2*)(src + (size_t)idx2 * 2);
    __half2 h; h.x = __float2half_rn(v.x); h.y = __float2half_rn(v.y);
    *(__half2*)(dst + (size_t)idx2 * 2) = h;
}

// ---------------- HMMA GEMM: out = Xh @ Wh^T ----------------
// 512 threads, 16 warps as 2(m) x 8(n); warp tile 64x32; 4-stage cp.async pipeline.
__global__ __launch_bounds__(512, 1) void mma_gemm_kernel(
    const __half* __restrict__ A,
    const __half* __restrict__ B,
    float* __restrict__ out)
{
    extern __shared__ __align__(128) char sm[];
    const unsigned smb = smem_u32(sm);
    const int tid  = threadIdx.x;
    const int wid  = tid >> 5, lane = tid & 31;
    const int wm   = wid & 1;          // 0..1 (m)
    const int wn   = wid >> 1;         // 0..7 (n)
    const int trow0 = blockIdx.y * BM;
    const int ncol0 = blockIdx.x * BN;

    const int slot = tid & 7;
    const int rr0  = tid >> 3;         // 0..63
    const __half* aP = A + (size_t)(trow0 + rr0) * KC + slot * 8;
    const __half* bP = B + (size_t)(ncol0 + rr0) * KC + slot * 8;
    const unsigned dBase = rr0 * LDSB + slot * 16;

    const unsigned lrow = lane & 15, lhalf = lane >> 4;
    const unsigned aBase = smb + (wm * 64 + lrow) * LDSB + lhalf * 16;
    const unsigned bBase = smb + ABYTES + (wn * 32 + lrow) * LDSB + lhalf * 16;

    float acc[4][4][4];
#pragma unroll
    for (int i = 0; i < 4; i++)
#pragma unroll
        for (int j = 0; j < 4; j++)
#pragma unroll
            for (int r = 0; r < 4; r++) acc[i][j][r] = 0.f;

#pragma unroll
    for (int c = 0; c < 3; c++) {
        unsigned d = smb + c * STAGEB + dBase;
        const __half* ap = aP + c * BK;
        const __half* bp = bP + c * BK;
#pragma unroll
        for (int i = 0; i < 2; i++) { cp16(d, ap); ap += 64 * KC; d += 64 * LDSB; }
#pragma unroll
        for (int i = 0; i < 4; i++) { cp16(d, bp); bp += 64 * KC; d += 64 * LDSB; }
        cp_commit();
    }

    for (int c = 0; c < NCH; c++) {
        cp_wait2();
        __syncthreads();

        int m = c + 3;
        if (m < NCH) {
            unsigned d = smb + (m & 3) * STAGEB + dBase;
            const __half* ap = aP + m * BK;
            const __half* bp = bP + m * BK;
#pragma unroll
            for (int i = 0; i < 2; i++) { cp16(d, ap); ap += 64 * KC; d += 64 * LDSB; }
#pragma unroll
            for (int i = 0; i < 4; i++) { cp16(d, bp); bp += 64 * KC; d += 64 * LDSB; }
        }
        cp_commit();

        unsigned soff = (unsigned)(c & 3) * STAGEB;
#pragma unroll
        for (int ks = 0; ks < 4; ks++) {
            unsigned a[4][4], b[2][4];
#pragma unroll
            for (int mi = 0; mi < 4; mi++)
                ldsm4(a[mi], aBase + soff + mi * (16 * LDSB) + ks * 32);
#pragma unroll
            for (int nj = 0; nj < 2; nj++)
                ldsm4(b[nj], bBase + soff + nj * (16 * LDSB) + ks * 32);
#pragma unroll
            for (int mi = 0; mi < 4; mi++) {
#pragma unroll
                for (int nb = 0; nb < 2; nb++) {
                    mma16816(acc[mi][2*nb],   a[mi], b[nb][0], b[nb][2]);
                    mma16816(acc[mi][2*nb+1], a[mi], b[nb][1], b[nb][3]);
                }
            }
        }
    }

    const int r0 = trow0 + wm * 64 + (lane >> 2);
    const int cc = ncol0 + wn * 32 + (lane & 3) * 2;
#pragma unroll
    for (int mi = 0; mi < 4; mi++) {
#pragma unroll
        for (int ni = 0; ni < 4; ni++) {
            float* p0 = out + (size_t)(r0 + mi * 16) * H_DIM + cc + ni * 8;
            float* p1 = p0 + 8 * H_DIM;
            *(float2*)p0 = make_float2(acc[mi][ni][0], acc[mi][ni][1]);
            *(float2*)p1 = make_float2(acc[mi][ni][2], acc[mi][ni][3]);
        }
    }
}

// ---------------- final add: out += contrib ----------------
__global__ __launch_bounds__(256) void add_kernel(float* __restrict__ out) {
    size_t i = (size_t)blockIdx.x * 256 + threadIdx.x;
    float4* o = (float4*)out;
    const float4* c = (const float4*)g_contrib;
    float4 a = o[i], b = c[i];
    a.x += b.x; a.y += b.y; a.z += b.z; a.w += b.w;
    o[i] = a;
}

// ---------------- tiny setup kernels ----------------
__global__ void zero_kernel() {
    int i = blockIdx.x * 1024 + threadIdx.x;
    if (i < H_DIM) g_counts[i] = 0;
    if (i < 64)    g_paircnt[i] = 0;
}
__global__ void hist_kernel(const int* __restrict__ mask) {
    int s = blockIdx.x * blockDim.x + threadIdx.x;
    if (s < NS_NUM) atomicAdd(&g_counts[mask[s] >> H_SHIFT], 1);
}
__global__ void scan_kernel() {
    __shared__ int chunk[256];
    int tid = threadIdx.x;
    int base = tid * 8;
    int local[8]; int s = 0;
#pragma unroll
    for (int c = 0; c < 8; c++) { local[c] = g_counts[base + c]; s += local[c]; }
    chunk[tid] = s;
    __syncthreads();
    if (tid == 0) {
        int run = 0;
        for (int i = 0; i < 256; i++) { int t = chunk[i]; chunk[i] = run; run += t; }
        g_rowptr[H_DIM] = run;
    }
    __syncthreads();
    int run = chunk[tid];
#pragma unroll
    for (int c = 0; c < 8; c++) {
        g_rowptr[base + c]  = run;
        g_offsets[base + c] = run;
        run += local[c];
    }
}
// scatter: entry-major weights (one 32B sector per entry) + cols
__global__ void scatter_kernel(const int* __restrict__ mask) {
    int s = blockIdx.x * blockDim.x + threadIdx.x;
    if (s >= NS_NUM) return;
    int m = mask[s];
    int r = m >> H_SHIFT;
    int c = m & H_MASK;
    int pos = atomicAdd(&g_offsets[r], 1);
    g_colsrt[pos] = (unsigned short)c;
    float4 lo = make_float4(g_weighted[0 * NS_NUM + s], g_weighted[1 * NS_NUM + s],
                            g_weighted[2 * NS_NUM + s], g_weighted[3 * NS_NUM + s]);
    float4 hi = make_float4(g_weighted[4 * NS_NUM + s], g_weighted[5 * NS_NUM + s],
                            g_weighted[6 * NS_NUM + s], g_weighted[7 * NS_NUM + s]);
    float4* dst = (float4*)(g_wsrtT + (size_t)pos * E_NUM);
    dst[0] = lo;
    dst[1] = hi;
}

// pair grouping: padded (to 4) exclusive scan over the 64 (e0,e1) pair counts
__global__ void pair_scan_kernel() {
    __shared__ int ptr[65];
    int tid = threadIdx.x;
    if (tid == 0) {
        int run = 0;
        for (int k = 0; k < 64; k++) {
            ptr[k] = run;
            run += ((g_paircnt[k] + 3) >> 2) << 2;
        }
        ptr[64] = run;
        g_total_blocks = run >> 2;
    }
    __syncthreads();
    for (int i = tid; i < 64; i += 256) g_pairoff[i] = ptr[i];
    for (int i = tid; i < PADMAX; i += 256) g_tokord[i] = -1;
    for (int k = tid; k < 64; k += 256) {
        int b0 = ptr[k] >> 2, b1 = ptr[k + 1] >> 2;
        for (int b = b0; b < b1; b++) g_blkpair[b] = k;
    }
}
__global__ void pair_scatter_kernel() {
    int t = blockIdx.x * blockDim.x + threadIdx.x;
    if (t >= T_TOK) return;
    int key = g_e0[t] * 8 + g_e1[t];
    int pos = atomicAdd(&g_pairoff[key], 1);
    g_tokord[pos] = t;
}

// ---------------- weighted: single pass over atoms, all 8 experts ----------------
__global__ __launch_bounds__(256) void weighted_kernel(
    const float* __restrict__ eaw, const float* __restrict__ atoms,
    const float* __restrict__ importance)
{
    __shared__ float wsm[E_NUM][A_NUM];
    int tid = threadIdx.x;
    int w = tid >> 5, lane = tid & 31;
    {
        float v0 = eaw[w * A_NUM + lane];
        float v1 = eaw[w * A_NUM + 32 + lane];
        float mx = fmaxf(v0, v1);
#pragma unroll
        for (int o = 16; o; o >>= 1) mx = fmaxf(mx, __shfl_xor_sync(0xffffffffu, mx, o));
        float e0 = expf(v0 - mx), e1 = expf(v1 - mx);
        float sm = e0 + e1;
#pragma unroll
        for (int o = 16; o; o >>= 1) sm += __shfl_xor_sync(0xffffffffu, sm, o);
        float inv = 1.f / sm;
        wsm[w][lane]      = e0 * inv;
        wsm[w][lane + 32] = e1 * inv;
    }
    __syncthreads();

    int s = blockIdx.x * 256 + tid;
    float acc[E_NUM];
#pragma unroll
    for (int e = 0; e < E_NUM; e++) acc[e] = 0.f;
#pragma unroll 4
    for (int a = 0; a < A_NUM; a++) {
        float va = atoms[a * NS_NUM + s];
#pragma unroll
        for (int e = 0; e < E_NUM; e++) acc[e] += wsm[e][a] * va;
    }
#pragma unroll
    for (int e = 0; e < E_NUM; e++) {
        float imp = importance[e * NS_NUM + s];
        g_weighted[e * NS_NUM + s] = acc[e] * (1.f / (1.f + expf(-imp)));
    }
}

// ---------------- gating: smem-free, warp-per-token ----------------
__global__ __launch_bounds__(256) void gate_kernel(
    const float* __restrict__ x, const float* __restrict__ gw)
{
    int t = blockIdx.x * 8 + (threadIdx.x >> 5);
    int lane = threadIdx.x & 31;
    const float4* xp = (const float4*)(x + (size_t)t * H_DIM);
    const float4* gp = (const float4*)gw;

    float acc[E_NUM];
#pragma unroll
    for (int e = 0; e < E_NUM; e++) acc[e] = 0.f;
#pragma unroll 4
    for (int i = 0; i < 16; i++) {
        float4 v = xp[lane + i * 32];
#pragma unroll
        for (int e = 0; e < E_NUM; e++) {
            float4 g = __ldg(&gp[e * 512 + lane + i * 32]);
            acc[e] += v.x * g.x + v.y * g.y + v.z * g.z + v.w * g.w;
        }
    }
#pragma unroll
    for (int e = 0; e < E_NUM; e++)
#pragma unroll
        for (int o = 16; o; o >>= 1)
            acc[e] += __shfl_xor_sync(0xffffffffu, acc[e], o);

    if (lane == 0) {
        float v[E_NUM];
#pragma unroll
        for (int e = 0; e < E_NUM; e++) v[e] = fminf(50.f, fmaxf(-50.f, acc[e]));
        int i0 = 0;
#pragma unroll
        for (int e = 1; e < E_NUM; e++) if (v[e] > v[i0]) i0 = e;
        int i1 = (i0 == 0) ? 1 : 0;
#pragma unroll
        for (int e = 0; e < E_NUM; e++) if (e != i0 && v[e] > v[i1]) i1 = e;
        float d = expf(v[i1] - v[i0]);
        float inv = 1.f / (1.f + d);
        g_e0[t] = i0; g_e1[t] = i1;
        g_rw0[t] = inv; g_rw1[t] = d * inv;
        atomicAdd(&g_paircnt[i0 * 8 + i1], 1);
    }
}

// ---------------- sparse contrib v7: sparse4 + entry-major weights, writes contrib ----------------
#define PLANE    2056
#define SP7_SMEM (4 * PLANE * 4 + 64)

__global__ __launch_bounds__(256, 4) void sparse7_kernel(
    const float* __restrict__ x)
{
    extern __shared__ char sm7[];
    float* xs  = (float*)sm7;                 // 4 planes of PLANE floats
    float* r0s = (float*)(sm7 + 4 * PLANE * 4);
    int*   tks = (int*)(r0s + 4);

    int b = blockIdx.x;
    if (b >= g_total_blocks) return;
    int pair = g_blkpair[b];
    const int e0i = pair >> 3, e1i = pair & 7;
    const float* wT = g_wsrtT;
    int tid = threadIdx.x;

    if (tid < 4) {
        int tok = g_tokord[b * 4 + tid];
        tks[tid] = tok;
        r0s[tid] = tok >= 0 ? g_rw0[tok] : 0.f;
    }
    __syncthreads();

    int tk[4]; float r0v[4];
#pragma unroll
    for (int t = 0; t < 4; t++) { tk[t] = tks[t]; r0v[t] = r0s[t]; }

    // stage x rows into planes (coalesced, conflict-free)
#pragma unroll 1
    for (int t = 0; t < 4; t++) {
        float* pl = xs + t * PLANE;
        if (tk[t] >= 0) {
            const float* xp = x + (size_t)tk[t] * H_DIM;
            for (int i = tid; i < H_DIM; i += 256) pl[i] = xp[i];
        } else {
            for (int i = tid; i < H_DIM; i += 256) pl[i] = 0.f;
        }
    }
    __syncthreads();

    float acc[8][4];
#pragma unroll
    for (int rr = 0; rr < 8; rr++)
#pragma unroll
        for (int t = 0; t < 4; t++) acc[rr][t] = 0.f;

#pragma unroll 1
    for (int rr = 0; rr < 8; rr++) {
        int row = tid + rr * 256;              // adjacent lanes -> adjacent rows
        int p    = g_rowptr[row];
        int pend = g_rowptr[row + 1];
#pragma unroll 4
        for (; p < pend; p++) {
            const float* wp = wT + (size_t)p * E_NUM;
            float w0p = __ldg(wp + e0i);       // same 32B sector as w1p
            float w1p = __ldg(wp + e1i);
            int cidx = (int)__ldg(g_colsrt + p);
            float dd = w0p - w1p;
#pragma unroll
            for (int t = 0; t < 4; t++) {
                float comb = fmaf(r0v[t], dd, w1p);     // r0*w0 + (1-r0)*w1
                acc[rr][t] = fmaf(xs[t * PLANE + cidx], comb, acc[rr][t]);
            }
        }
    }

    // write contrib (coalesced per (t, rr))
#pragma unroll 1
    for (int t = 0; t < 4; t++) {
        if (tk[t] < 0) continue;
        float* op = g_contrib + (size_t)tk[t] * H_DIM;
#pragma unroll
        for (int rr = 0; rr < 8; rr++) {
            int row = tid + rr * 256;
            op[row] = acc[rr][t];
        }
    }
}

// ---------------- launch ----------------
extern "C" void kernel_launch(void* const* d_in, const int* in_sizes, int n_in,
                              void* d_out, int out_size)
{
    const float* x     = (const float*)d_in[0];
    const float* gw    = (const float*)d_in[1];
    const float* W     = (const float*)d_in[2];
    const float* atoms = (const float*)d_in[3];
    const float* eaw   = (const float*)d_in[4];
    const float* imp   = (const float*)d_in[5];
    const int*   mask  = (const int*)d_in[6];
    float* out = (float*)d_out;

    (void)in_sizes; (void)n_in; (void)out_size;

    void *xh_p = nullptr, *wh_p = nullptr;
    cudaGetSymbolAddress(&xh_p, g_xh);
    cudaGetSymbolAddress(&wh_p, g_wh);

    cudaFuncSetAttribute(mma_gemm_kernel,
                         cudaFuncAttributeMaxDynamicSharedMemorySize, SMEM_MMA);

    cudaStream_t sd = g_fork_res.side;

    cudaEventRecord(g_fork_res.fork, 0);
    cudaStreamWaitEvent(sd, g_fork_res.fork, 0);

    // launches 1,2: fp16 converts (main)
    convert_fp16_kernel<<<(T_TOK * H_DIM / 2) / 256, 256>>>(x, (__half*)xh_p);
    convert_fp16_kernel<<<(H_DIM * H_DIM / 2) / 256, 256>>>(W, (__half*)wh_p);
    // launch 3: zero (side)
    zero_kernel<<<2, 1024, 0, sd>>>();
    // launch 4: GEMM (main) — profiled slot
    mma_gemm_kernel<<<dim3(H_DIM / BN, T_TOK / BM), 512, SMEM_MMA>>>(
        (const __half*)xh_p, (const __half*)wh_p, out);

    // side branch: full sparse path into g_contrib; sparse7 overlaps GEMM's tail wave
    hist_kernel<<<NS_NUM / 1024, 1024, 0, sd>>>(mask);
    weighted_kernel<<<NS_NUM / 256, 256, 0, sd>>>(eaw, atoms, imp);
    gate_kernel<<<T_TOK / 8, 256, 0, sd>>>(x, gw);
    scan_kernel<<<1, 256, 0, sd>>>();
    pair_scan_kernel<<<1, 256, 0, sd>>>();
    pair_scatter_kernel<<<T_TOK / 256, 256, 0, sd>>>();
    scatter_kernel<<<NS_NUM / 1024, 1024, 0, sd>>>(mask);
    sparse7_kernel<<<MAXBLK, 256, SP7_SMEM, sd>>>(x);
    cudaEventRecord(g_fork_res.join, sd);

    // join, then out += contrib
    cudaStreamWaitEvent(0, g_fork_res.join, 0);
    add_kernel<<<(T_TOK * H_DIM / 4) / 256, 256>>>(out);
}

// round 14
// speedup vs baseline: 1.1214x; 1.1214x over previous
#include <cuda_runtime.h>
#include <cuda_fp16.h>
#include <math.h>

// Problem constants (fixed shapes: B=2,S=2048,H=2048,E=8,A=64,NS=16384)
#define T_TOK   4096
#define H_DIM   2048
#define E_NUM   8
#define A_NUM   64
#define NS_NUM  16384
#define H_SHIFT 11
#define H_MASK  2047
#define PADMAX  4608
#define MAXBLK  1152

// GEMM: C[T,H] = fp16(x) @ fp16(W)^T, K = 2048, fp32 accumulate
#define KC      2048
#define BM      128
#define BN      256
#define BK      64
#define NCH     (KC / BK)            // 32
#define LDSB    144                  // smem row stride bytes (64 fp16 + 16 pad)
#define ABYTES  (BM * LDSB)          // 18432
#define STAGEB  ((BM + BN) * LDSB)   // 55296
#define NSTG    4
#define SMEM_MMA (NSTG * STAGEB)     // 221184

// ---------------- device scratch (no allocations allowed) ----------------
__device__ __half         g_xh[(size_t)T_TOK * KC];     // 16MB fp16(x)
__device__ __half         g_wh[(size_t)H_DIM * KC];     // 8MB  fp16(W)
__device__ float          g_weighted[E_NUM * NS_NUM];
__device__ float          g_wsrt[E_NUM * NS_NUM];       // weighted, CSR entry order
__device__ unsigned short g_colsrt[NS_NUM];             // col per CSR entry
__device__ int            g_counts[H_DIM];
__device__ int            g_rowptr[H_DIM + 1];
__device__ int            g_offsets[H_DIM];
__device__ int            g_e0[T_TOK];
__device__ int            g_e1[T_TOK];
__device__ float          g_rw0[T_TOK];
__device__ float          g_rw1[T_TOK];
// pair grouping (4 tokens per block)
__device__ int            g_paircnt[64];
__device__ int            g_pairoff[64];
__device__ int            g_tokord[PADMAX];
__device__ int            g_blkpair[MAXBLK];
__device__ int            g_total_blocks;

// ---------------- static stream/event resources (created pre-checkpoint) ----------------
struct GraphForkResources {
    cudaStream_t side;
    cudaEvent_t  fork, gemm_done, join;
    GraphForkResources() {
        cudaStreamCreateWithFlags(&side, cudaStreamNonBlocking);
        cudaEventCreateWithFlags(&fork, cudaEventDisableTiming);
        cudaEventCreateWithFlags(&gemm_done, cudaEventDisableTiming);
        cudaEventCreateWithFlags(&join, cudaEventDisableTiming);
    }
};
static GraphForkResources g_fork_res;

// ---------------- ptx helpers (compute_80-level, safe on compute_103) ----------------
__device__ __forceinline__ unsigned smem_u32(const void* p) {
    unsigned r;
    asm("{ .reg .u64 t; cvta.to.shared.u64 t, %1; cvt.u32.u64 %0, t; }" : "=r"(r) : "l"(p));
    return r;
}
__device__ __forceinline__ void cp16(unsigned dst, const void* src) {
    asm volatile("cp.async.cg.shared.global [%0], [%1], 16;\n" :: "r"(dst), "l"(src));
}
__device__ __forceinline__ void cp_commit() { asm volatile("cp.async.commit_group;\n" ::: "memory"); }
__device__ __forceinline__ void cp_wait2()  { asm volatile("cp.async.wait_group 2;\n" ::: "memory"); }
__device__ __forceinline__ void ldsm4(unsigned* r, unsigned addr) {
    asm volatile("ldmatrix.sync.aligned.m8n8.x4.shared.b16 {%0,%1,%2,%3}, [%4];"
                 : "=r"(r[0]), "=r"(r[1]), "=r"(r[2]), "=r"(r[3]) : "r"(addr));
}
__device__ __forceinline__ void mma16816(float* d, const unsigned* a, unsigned b0, unsigned b1) {
    asm volatile(
        "mma.sync.aligned.m16n8k16.row.col.f32.f16.f16.f32 "
        "{%0,%1,%2,%3}, {%4,%5,%6,%7}, {%8,%9}, {%0,%1,%2,%3};"
        : "+f"(d[0]), "+f"(d[1]), "+f"(d[2]), "+f"(d[3])
        : "r"(a[0]), "r"(a[1]), "r"(a[2]), "r"(a[3]), "r"(b0), "r"(b1));
}

// ---------------- fp16 conversion (x and W share row length 2048) ----------------
__global__ __launch_bounds__(256) void convert_fp16_kernel(
    const float* __restrict__ src, __half* __restrict__ dst)
{
    int idx2 = blockIdx.x * 256 + threadIdx.x;          // float2 index
    float2 v = *(const float2*)(src + (size_t)idx2 * 2);
    __half2 h; h.x = __float2half_rn(v.x); h.y = __float2half_rn(v.y);
    *(__half2*)(dst + (size_t)idx2 * 2) = h;
}

// ---------------- HMMA GEMM: out = Xh @ Wh^T ----------------
// 512 threads, 16 warps as 2(m) x 8(n); warp tile 64x32; 4-stage cp.async pipeline.
__global__ __launch_bounds__(512, 1) void mma_gemm_kernel(
    const __half* __restrict__ A,
    const __half* __restrict__ B,
    float* __restrict__ out)
{
    extern __shared__ __align__(128) char sm[];
    const unsigned smb = smem_u32(sm);
    const int tid  = threadIdx.x;
    const int wid  = tid >> 5, lane = tid & 31;
    const int wm   = wid & 1;          // 0..1 (m)
    const int wn   = wid >> 1;         // 0..7 (n)
    const int trow0 = blockIdx.y * BM;
    const int ncol0 = blockIdx.x * BN;

    const int slot = tid & 7;
    const int rr0  = tid >> 3;         // 0..63
    const __half* aP = A + (size_t)(trow0 + rr0) * KC + slot * 8;
    const __half* bP = B + (size_t)(ncol0 + rr0) * KC + slot * 8;
    const unsigned dBase = rr0 * LDSB + slot * 16;

    const unsigned lrow = lane & 15, lhalf = lane >> 4;
    const unsigned aBase = smb + (wm * 64 + lrow) * LDSB + lhalf * 16;
    const unsigned bBase = smb + ABYTES + (wn * 32 + lrow) * LDSB + lhalf * 16;

    float acc[4][4][4];
#pragma unroll
    for (int i = 0; i < 4; i++)
#pragma unroll
        for (int j = 0; j < 4; j++)
#pragma unroll
            for (int r = 0; r < 4; r++) acc[i][j][r] = 0.f;

#pragma unroll
    for (int c = 0; c < 3; c++) {
        unsigned d = smb + c * STAGEB + dBase;
        const __half* ap = aP + c * BK;
        const __half* bp = bP + c * BK;
#pragma unroll
        for (int i = 0; i < 2; i++) { cp16(d, ap); ap += 64 * KC; d += 64 * LDSB; }
#pragma unroll
        for (int i = 0; i < 4; i++) { cp16(d, bp); bp += 64 * KC; d += 64 * LDSB; }
        cp_commit();
    }

    for (int c = 0; c < NCH; c++) {
        cp_wait2();
        __syncthreads();

        int m = c + 3;
        if (m < NCH) {
            unsigned d = smb + (m & 3) * STAGEB + dBase;
            const __half* ap = aP + m * BK;
            const __half* bp = bP + m * BK;
#pragma unroll
            for (int i = 0; i < 2; i++) { cp16(d, ap); ap += 64 * KC; d += 64 * LDSB; }
#pragma unroll
            for (int i = 0; i < 4; i++) { cp16(d, bp); bp += 64 * KC; d += 64 * LDSB; }
        }
        cp_commit();

        unsigned soff = (unsigned)(c & 3) * STAGEB;
#pragma unroll
        for (int ks = 0; ks < 4; ks++) {
            unsigned a[4][4], b[2][4];
#pragma unroll
            for (int mi = 0; mi < 4; mi++)
                ldsm4(a[mi], aBase + soff + mi * (16 * LDSB) + ks * 32);
#pragma unroll
            for (int nj = 0; nj < 2; nj++)
                ldsm4(b[nj], bBase + soff + nj * (16 * LDSB) + ks * 32);
#pragma unroll
            for (int mi = 0; mi < 4; mi++) {
#pragma unroll
                for (int nb = 0; nb < 2; nb++) {
                    mma16816(acc[mi][2*nb],   a[mi], b[nb][0], b[nb][2]);
                    mma16816(acc[mi][2*nb+1], a[mi], b[nb][1], b[nb][3]);
                }
            }
        }
    }

    const int r0 = trow0 + wm * 64 + (lane >> 2);
    const int cc = ncol0 + wn * 32 + (lane & 3) * 2;
#pragma unroll
    for (int mi = 0; mi < 4; mi++) {
#pragma unroll
        for (int ni = 0; ni < 4; ni++) {
            float* p0 = out + (size_t)(r0 + mi * 16) * H_DIM + cc + ni * 8;
            float* p1 = p0 + 8 * H_DIM;
            *(float2*)p0 = make_float2(acc[mi][ni][0], acc[mi][ni][1]);
            *(float2*)p1 = make_float2(acc[mi][ni][2], acc[mi][ni][3]);
        }
    }
}

// ---------------- tiny setup kernels ----------------
__global__ void zero_kernel() {
    int i = blockIdx.x * 1024 + threadIdx.x;
    if (i < H_DIM) g_counts[i] = 0;
    if (i < 64)    g_paircnt[i] = 0;
}
__global__ void hist_kernel(const int* __restrict__ mask) {
    int s = blockIdx.x * blockDim.x + threadIdx.x;
    if (s < NS_NUM) atomicAdd(&g_counts[mask[s] >> H_SHIFT], 1);
}
__global__ void scan_kernel() {
    __shared__ int chunk[256];
    int tid = threadIdx.x;
    int base = tid * 8;
    int local[8]; int s = 0;
#pragma unroll
    for (int c = 0; c < 8; c++) { local[c] = g_counts[base + c]; s += local[c]; }
    chunk[tid] = s;
    __syncthreads();
    if (tid == 0) {
        int run = 0;
        for (int i = 0; i < 256; i++) { int t = chunk[i]; chunk[i] = run; run += t; }
        g_rowptr[H_DIM] = run;
    }
    __syncthreads();
    int run = chunk[tid];
#pragma unroll
    for (int c = 0; c < 8; c++) {
        g_rowptr[base + c]  = run;
        g_offsets[base + c] = run;
        run += local[c];
    }
}
__global__ void scatter_kernel(const int* __restrict__ mask) {
    int s = blockIdx.x * blockDim.x + threadIdx.x;
    if (s >= NS_NUM) return;
    int m = mask[s];
    int r = m >> H_SHIFT;
    int c = m & H_MASK;
    int pos = atomicAdd(&g_offsets[r], 1);
    g_colsrt[pos] = (unsigned short)c;
#pragma unroll
    for (int e = 0; e < E_NUM; e++)
        g_wsrt[e * NS_NUM + pos] = g_weighted[e * NS_NUM + s];
}

// pair grouping: padded (to 4) exclusive scan over the 64 (e0,e1) pair counts
__global__ void pair_scan_kernel() {
    __shared__ int ptr[65];
    int tid = threadIdx.x;
    if (tid == 0) {
        int run = 0;
        for (int k = 0; k < 64; k++) {
            ptr[k] = run;
            run += ((g_paircnt[k] + 3) >> 2) << 2;
        }
        ptr[64] = run;
        g_total_blocks = run >> 2;
    }
    __syncthreads();
    for (int i = tid; i < 64; i += 256) g_pairoff[i] = ptr[i];
    for (int i = tid; i < PADMAX; i += 256) g_tokord[i] = -1;
    for (int k = tid; k < 64; k += 256) {
        int b0 = ptr[k] >> 2, b1 = ptr[k + 1] >> 2;
        for (int b = b0; b < b1; b++) g_blkpair[b] = k;
    }
}
__global__ void pair_scatter_kernel() {
    int t = blockIdx.x * blockDim.x + threadIdx.x;
    if (t >= T_TOK) return;
    int key = g_e0[t] * 8 + g_e1[t];
    int pos = atomicAdd(&g_pairoff[key], 1);
    g_tokord[pos] = t;
}

// ---------------- weighted: single pass over atoms, all 8 experts ----------------
__global__ __launch_bounds__(256) void weighted_kernel(
    const float* __restrict__ eaw, const float* __restrict__ atoms,
    const float* __restrict__ importance)
{
    __shared__ float wsm[E_NUM][A_NUM];
    int tid = threadIdx.x;
    int w = tid >> 5, lane = tid & 31;
    {
        float v0 = eaw[w * A_NUM + lane];
        float v1 = eaw[w * A_NUM + 32 + lane];
        float mx = fmaxf(v0, v1);
#pragma unroll
        for (int o = 16; o; o >>= 1) mx = fmaxf(mx, __shfl_xor_sync(0xffffffffu, mx, o));
        float e0 = expf(v0 - mx), e1 = expf(v1 - mx);
        float sm = e0 + e1;
#pragma unroll
        for (int o = 16; o; o >>= 1) sm += __shfl_xor_sync(0xffffffffu, sm, o);
        float inv = 1.f / sm;
        wsm[w][lane]      = e0 * inv;
        wsm[w][lane + 32] = e1 * inv;
    }
    __syncthreads();

    int s = blockIdx.x * 256 + tid;
    float acc[E_NUM];
#pragma unroll
    for (int e = 0; e < E_NUM; e++) acc[e] = 0.f;
#pragma unroll 4
    for (int a = 0; a < A_NUM; a++) {
        float va = atoms[a * NS_NUM + s];
#pragma unroll
        for (int e = 0; e < E_NUM; e++) acc[e] += wsm[e][a] * va;
    }
#pragma unroll
    for (int e = 0; e < E_NUM; e++) {
        float imp = importance[e * NS_NUM + s];
        g_weighted[e * NS_NUM + s] = acc[e] * (1.f / (1.f + expf(-imp)));
    }
}

// ---------------- gating: smem-free, warp-per-token ----------------
__global__ __launch_bounds__(256) void gate_kernel(
    const float* __restrict__ x, const float* __restrict__ gw)
{
    int t = blockIdx.x * 8 + (threadIdx.x >> 5);
    int lane = threadIdx.x & 31;
    const float4* xp = (const float4*)(x + (size_t)t * H_DIM);
    const float4* gp = (const float4*)gw;

    float acc[E_NUM];
#pragma unroll
    for (int e = 0; e < E_NUM; e++) acc[e] = 0.f;
#pragma unroll 4
    for (int i = 0; i < 16; i++) {
        float4 v = xp[lane + i * 32];
#pragma unroll
        for (int e = 0; e < E_NUM; e++) {
            float4 g = __ldg(&gp[e * 512 + lane + i * 32]);
            acc[e] += v.x * g.x + v.y * g.y + v.z * g.z + v.w * g.w;
        }
    }
#pragma unroll
    for (int e = 0; e < E_NUM; e++)
#pragma unroll
        for (int o = 16; o; o >>= 1)
            acc[e] += __shfl_xor_sync(0xffffffffu, acc[e], o);

    if (lane == 0) {
        float v[E_NUM];
#pragma unroll
        for (int e = 0; e < E_NUM; e++) v[e] = fminf(50.f, fmaxf(-50.f, acc[e]));
        int i0 = 0;
#pragma unroll
        for (int e = 1; e < E_NUM; e++) if (v[e] > v[i0]) i0 = e;
        int i1 = (i0 == 0) ? 1 : 0;
#pragma unroll
        for (int e = 0; e < E_NUM; e++) if (e != i0 && v[e] > v[i1]) i1 = e;
        float d = expf(v[i1] - v[i0]);
        float inv = 1.f / (1.f + d);
        g_e0[t] = i0; g_e1[t] = i1;
        g_rw0[t] = inv; g_rw1[t] = d * inv;
        atomicAdd(&g_paircnt[i0 * 8 + i1], 1);
    }
}

// ---------------- sparse contrib v8: sparse4 layout, 6 blocks/SM via 2-pass rows ----------------
#define PLANE    2056
#define SP8_SMEM (4 * PLANE * 4 + 64)

__global__ __launch_bounds__(256, 6) void sparse8_kernel(
    const float* __restrict__ x, float* __restrict__ out)
{
    extern __shared__ char sm8[];
    float* xs  = (float*)sm8;                 // 4 planes of PLANE floats
    float* r0s = (float*)(sm8 + 4 * PLANE * 4);
    int*   tks = (int*)(r0s + 4);

    int b = blockIdx.x;
    if (b >= g_total_blocks) return;
    int pair = g_blkpair[b];
    const float* w0 = g_wsrt + (pair >> 3) * NS_NUM;
    const float* w1 = g_wsrt + (pair & 7) * NS_NUM;
    int tid = threadIdx.x;

    if (tid < 4) {
        int tok = g_tokord[b * 4 + tid];
        tks[tid] = tok;
        r0s[tid] = tok >= 0 ? g_rw0[tok] : 0.f;
    }
    __syncthreads();

    float r0v[4];
#pragma unroll
    for (int t = 0; t < 4; t++) r0v[t] = r0s[t];

    // stage x rows into planes (coalesced, conflict-free)
#pragma unroll 1
    for (int t = 0; t < 4; t++) {
        float* pl = xs + t * PLANE;
        int tok = tks[t];
        if (tok >= 0) {
            const float* xp = x + (size_t)tok * H_DIM;
            for (int i = tid; i < H_DIM; i += 256) pl[i] = xp[i];
        } else {
            for (int i = tid; i < H_DIM; i += 256) pl[i] = 0.f;
        }
    }
    __syncthreads();

    // two passes of 4 rows each -> acc fits in 16 regs (6 blocks/SM)
#pragma unroll 1
    for (int rp = 0; rp < 2; rp++) {
        float acc[4][4];
#pragma unroll
        for (int rr = 0; rr < 4; rr++)
#pragma unroll
            for (int t = 0; t < 4; t++) acc[rr][t] = 0.f;

#pragma unroll 1
        for (int rr = 0; rr < 4; rr++) {
            int row = tid + (rp * 4 + rr) * 256;   // adjacent lanes -> adjacent rows
            int p    = g_rowptr[row];
            int pend = g_rowptr[row + 1];
#pragma unroll 4
            for (; p < pend; p++) {
                float w0p = __ldg(w0 + p);
                float w1p = __ldg(w1 + p);
                int cidx = (int)__ldg(g_colsrt + p);
                float dd = w0p - w1p;
#pragma unroll
                for (int t = 0; t < 4; t++) {
                    float comb = fmaf(r0v[t], dd, w1p);     // r0*w0 + (1-r0)*w1
                    acc[rr][t] = fmaf(xs[t * PLANE + cidx], comb, acc[rr][t]);
                }
            }
        }

        // direct add into out (GEMM result already there; ordered via gemm_done event)
#pragma unroll 1
        for (int t = 0; t < 4; t++) {
            int tok = tks[t];
            if (tok < 0) continue;
            float* op = out + (size_t)tok * H_DIM;
#pragma unroll
            for (int rr = 0; rr < 4; rr++) {
                int row = tid + (rp * 4 + rr) * 256;
                op[row] += acc[rr][t];
            }
        }
    }
}

// ---------------- launch ----------------
extern "C" void kernel_launch(void* const* d_in, const int* in_sizes, int n_in,
                              void* d_out, int out_size)
{
    const float* x     = (const float*)d_in[0];
    const float* gw    = (const float*)d_in[1];
    const float* W     = (const float*)d_in[2];
    const float* atoms = (const float*)d_in[3];
    const float* eaw   = (const float*)d_in[4];
    const float* imp   = (const float*)d_in[5];
    const int*   mask  = (const int*)d_in[6];
    float* out = (float*)d_out;

    (void)in_sizes; (void)n_in; (void)out_size;

    void *xh_p = nullptr, *wh_p = nullptr;
    cudaGetSymbolAddress(&xh_p, g_xh);
    cudaGetSymbolAddress(&wh_p, g_wh);

    cudaFuncSetAttribute(mma_gemm_kernel,
                         cudaFuncAttributeMaxDynamicSharedMemorySize, SMEM_MMA);

    cudaStream_t sd = g_fork_res.side;

    cudaEventRecord(g_fork_res.fork, 0);
    cudaStreamWaitEvent(sd, g_fork_res.fork, 0);

    // launches 1,2: fp16 converts (main)
    convert_fp16_kernel<<<(T_TOK * H_DIM / 2) / 256, 256>>>(x, (__half*)xh_p);
    convert_fp16_kernel<<<(H_DIM * H_DIM / 2) / 256, 256>>>(W, (__half*)wh_p);
    // launch 3: zero (side)
    zero_kernel<<<2, 1024, 0, sd>>>();
    // launch 4: GEMM (main) — profiled slot
    mma_gemm_kernel<<<dim3(H_DIM / BN, T_TOK / BM), 512, SMEM_MMA>>>(
        (const __half*)xh_p, (const __half*)wh_p, out);
    cudaEventRecord(g_fork_res.gemm_done, 0);

    // side branch: sparse prep overlaps GEMM; sparse8 waits for GEMM then adds into out
    hist_kernel<<<NS_NUM / 1024, 1024, 0, sd>>>(mask);
    weighted_kernel<<<NS_NUM / 256, 256, 0, sd>>>(eaw, atoms, imp);
    gate_kernel<<<T_TOK / 8, 256, 0, sd>>>(x, gw);
    scan_kernel<<<1, 256, 0, sd>>>();
    pair_scan_kernel<<<1, 256, 0, sd>>>();
    pair_scatter_kernel<<<T_TOK / 256, 256, 0, sd>>>();
    scatter_kernel<<<NS_NUM / 1024, 1024, 0, sd>>>(mask);
    cudaStreamWaitEvent(sd, g_fork_res.gemm_done, 0);
    sparse8_kernel<<<MAXBLK, 256, SP8_SMEM, sd>>>(x, out);
    cudaEventRecord(g_fork_res.join, sd);

    // join side branch back into the capture-origin stream
    cudaStreamWaitEvent(0, g_fork_res.join, 0);
}

// round 15
// speedup vs baseline: 1.1929x; 1.0637x over previous
#include <cuda_runtime.h>
#include <cuda_fp16.h>
#include <math.h>

// Problem constants (fixed shapes: B=2,S=2048,H=2048,E=8,A=64,NS=16384)
#define T_TOK   4096
#define H_DIM   2048
#define E_NUM   8
#define A_NUM   64
#define NS_NUM  16384
#define H_SHIFT 11
#define H_MASK  2047
#define PADMAX  4608
#define MAXBLK  1152

// GEMM: C[T,H] = fp16(x) @ fp16(W)^T, K = 2048, fp32 accumulate
#define KC      2048
#define BM      128
#define BN      256
#define BK      64
#define NCH     (KC / BK)            // 32
#define LDSB    144                  // smem row stride bytes (64 fp16 + 16 pad)
#define ABYTES  (BM * LDSB)          // 18432
#define STAGEB  ((BM + BN) * LDSB)   // 55296
#define NSTG    4
#define SMEM_MMA (NSTG * STAGEB)     // 221184

// ---------------- device scratch (no allocations allowed) ----------------
__device__ __half         g_xh[(size_t)T_TOK * KC];     // 16MB fp16(x)
__device__ __half         g_wh[(size_t)H_DIM * KC];     // 8MB  fp16(W)
__device__ float          g_weighted[E_NUM * NS_NUM];
__device__ float          g_wsrt[E_NUM * NS_NUM];       // weighted, CSR entry order
__device__ unsigned short g_colsrt[NS_NUM];             // col per CSR entry
__device__ uint2          g_pk[(size_t)64 * NS_NUM];    // 8MB packed {w0h,w1h,col} per pair
__device__ int            g_counts[H_DIM];
__device__ int            g_rowptr[H_DIM + 1];
__device__ int            g_offsets[H_DIM];
__device__ int            g_e0[T_TOK];
__device__ int            g_e1[T_TOK];
__device__ float          g_rw0[T_TOK];
__device__ float          g_rw1[T_TOK];
// pair grouping (4 tokens per block)
__device__ int            g_paircnt[64];
__device__ int            g_pairoff[64];
__device__ int            g_tokord[PADMAX];
__device__ int            g_blkpair[MAXBLK];
__device__ int            g_total_blocks;

// ---------------- static stream/event resources (created pre-checkpoint) ----------------
struct GraphForkResources {
    cudaStream_t side;
    cudaEvent_t  fork, gemm_done, join;
    GraphForkResources() {
        cudaStreamCreateWithFlags(&side, cudaStreamNonBlocking);
        cudaEventCreateWithFlags(&fork, cudaEventDisableTiming);
        cudaEventCreateWithFlags(&gemm_done, cudaEventDisableTiming);
        cudaEventCreateWithFlags(&join, cudaEventDisableTiming);
    }
};
static GraphForkResources g_fork_res;

// ---------------- ptx helpers (compute_80-level, safe on compute_103) ----------------
__device__ __forceinline__ unsigned smem_u32(const void* p) {
    unsigned r;
    asm("{ .reg .u64 t; cvta.to.shared.u64 t, %1; cvt.u32.u64 %0, t; }" : "=r"(r) : "l"(p));
    return r;
}
__device__ __forceinline__ void cp16(unsigned dst, const void* src) {
    asm volatile("cp.async.cg.shared.global [%0], [%1], 16;\n" :: "r"(dst), "l"(src));
}
__device__ __forceinline__ void cp_commit() { asm volatile("cp.async.commit_group;\n" ::: "memory"); }
__device__ __forceinline__ void cp_wait2()  { asm volatile("cp.async.wait_group 2;\n" ::: "memory"); }
__device__ __forceinline__ void ldsm4(unsigned* r, unsigned addr) {
    asm volatile("ldmatrix.sync.aligned.m8n8.x4.shared.b16 {%0,%1,%2,%3}, [%4];"
                 : "=r"(r[0]), "=r"(r[1]), "=r"(r[2]), "=r"(r[3]) : "r"(addr));
}
__device__ __forceinline__ void mma16816(float* d, const unsigned* a, unsigned b0, unsigned b1) {
    asm volatile(
        "mma.sync.aligned.m16n8k16.row.col.f32.f16.f16.f32 "
        "{%0,%1,%2,%3}, {%4,%5,%6,%7}, {%8,%9}, {%0,%1,%2,%3};"
        : "+f"(d[0]), "+f"(d[1]), "+f"(d[2]), "+f"(d[3])
        : "r"(a[0]), "r"(a[1]), "r"(a[2]), "r"(a[3]), "r"(b0), "r"(b1));
}

// ---------------- fp16 conversion (x and W share row length 2048) ----------------
__global__ __launch_bounds__(256) void convert_fp16_kernel(
    const float* __restrict__ src, __half* __restrict__ dst)
{
    int idx2 = blockIdx.x * 256 + threadIdx.x;          // float2 index
    float2 v = *(const float2*)(src + (size_t)idx2 * 2);
    __half2 h; h.x = __float2half_rn(v.x); h.y = __float2half_rn(v.y);
    *(__half2*)(dst + (size_t)idx2 * 2) = h;
}

// ---------------- HMMA GEMM: out = Xh @ Wh^T ----------------
// 512 threads, 16 warps as 2(m) x 8(n); warp tile 64x32; 4-stage cp.async pipeline.
__global__ __launch_bounds__(512, 1) void mma_gemm_kernel(
    const __half* __restrict__ A,
    const __half* __restrict__ B,
    float* __restrict__ out)
{
    extern __shared__ __align__(128) char sm[];
    const unsigned smb = smem_u32(sm);
    const int tid  = threadIdx.x;
    const int wid  = tid >> 5, lane = tid & 31;
    const int wm   = wid & 1;          // 0..1 (m)
    const int wn   = wid >> 1;         // 0..7 (n)
    const int trow0 = blockIdx.y * BM;
    const int ncol0 = blockIdx.x * BN;

    const int slot = tid & 7;
    const int rr0  = tid >> 3;         // 0..63
    const __half* aP = A + (size_t)(trow0 + rr0) * KC + slot * 8;
    const __half* bP = B + (size_t)(ncol0 + rr0) * KC + slot * 8;
    const unsigned dBase = rr0 * LDSB + slot * 16;

    const unsigned lrow = lane & 15, lhalf = lane >> 4;
    const unsigned aBase = smb + (wm * 64 + lrow) * LDSB + lhalf * 16;
    const unsigned bBase = smb + ABYTES + (wn * 32 + lrow) * LDSB + lhalf * 16;

    float acc[4][4][4];
#pragma unroll
    for (int i = 0; i < 4; i++)
#pragma unroll
        for (int j = 0; j < 4; j++)
#pragma unroll
            for (int r = 0; r < 4; r++) acc[i][j][r] = 0.f;

#pragma unroll
    for (int c = 0; c < 3; c++) {
        unsigned d = smb + c * STAGEB + dBase;
        const __half* ap = aP + c * BK;
        const __half* bp = bP + c * BK;
#pragma unroll
        for (int i = 0; i < 2; i++) { cp16(d, ap); ap += 64 * KC; d += 64 * LDSB; }
#pragma unroll
        for (int i = 0; i < 4; i++) { cp16(d, bp); bp += 64 * KC; d += 64 * LDSB; }
        cp_commit();
    }

    for (int c = 0; c < NCH; c++) {
        cp_wait2();
        __syncthreads();

        int m = c + 3;
        if (m < NCH) {
            unsigned d = smb + (m & 3) * STAGEB + dBase;
            const __half* ap = aP + m * BK;
            const __half* bp = bP + m * BK;
#pragma unroll
            for (int i = 0; i < 2; i++) { cp16(d, ap); ap += 64 * KC; d += 64 * LDSB; }
#pragma unroll
            for (int i = 0; i < 4; i++) { cp16(d, bp); bp += 64 * KC; d += 64 * LDSB; }
        }
        cp_commit();

        unsigned soff = (unsigned)(c & 3) * STAGEB;
#pragma unroll
        for (int ks = 0; ks < 4; ks++) {
            unsigned a[4][4], b[2][4];
#pragma unroll
            for (int mi = 0; mi < 4; mi++)
                ldsm4(a[mi], aBase + soff + mi * (16 * LDSB) + ks * 32);
#pragma unroll
            for (int nj = 0; nj < 2; nj++)
                ldsm4(b[nj], bBase + soff + nj * (16 * LDSB) + ks * 32);
#pragma unroll
            for (int mi = 0; mi < 4; mi++) {
#pragma unroll
                for (int nb = 0; nb < 2; nb++) {
                    mma16816(acc[mi][2*nb],   a[mi], b[nb][0], b[nb][2]);
                    mma16816(acc[mi][2*nb+1], a[mi], b[nb][1], b[nb][3]);
                }
            }
        }
    }

    const int r0 = trow0 + wm * 64 + (lane >> 2);
    const int cc = ncol0 + wn * 32 + (lane & 3) * 2;
#pragma unroll
    for (int mi = 0; mi < 4; mi++) {
#pragma unroll
        for (int ni = 0; ni < 4; ni++) {
            float* p0 = out + (size_t)(r0 + mi * 16) * H_DIM + cc + ni * 8;
            float* p1 = p0 + 8 * H_DIM;
            *(float2*)p0 = make_float2(acc[mi][ni][0], acc[mi][ni][1]);
            *(float2*)p1 = make_float2(acc[mi][ni][2], acc[mi][ni][3]);
        }
    }
}

// ---------------- tiny setup kernels ----------------
__global__ void zero_kernel() {
    int i = blockIdx.x * 1024 + threadIdx.x;
    if (i < H_DIM) g_counts[i] = 0;
    if (i < 64)    g_paircnt[i] = 0;
}
__global__ void hist_kernel(const int* __restrict__ mask) {
    int s = blockIdx.x * blockDim.x + threadIdx.x;
    if (s < NS_NUM) atomicAdd(&g_counts[mask[s] >> H_SHIFT], 1);
}
__global__ void scan_kernel() {
    __shared__ int chunk[256];
    int tid = threadIdx.x;
    int base = tid * 8;
    int local[8]; int s = 0;
#pragma unroll
    for (int c = 0; c < 8; c++) { local[c] = g_counts[base + c]; s += local[c]; }
    chunk[tid] = s;
    __syncthreads();
    if (tid == 0) {
        int run = 0;
        for (int i = 0; i < 256; i++) { int t = chunk[i]; chunk[i] = run; run += t; }
        g_rowptr[H_DIM] = run;
    }
    __syncthreads();
    int run = chunk[tid];
#pragma unroll
    for (int c = 0; c < 8; c++) {
        g_rowptr[base + c]  = run;
        g_offsets[base + c] = run;
        run += local[c];
    }
}
__global__ void scatter_kernel(const int* __restrict__ mask) {
    int s = blockIdx.x * blockDim.x + threadIdx.x;
    if (s >= NS_NUM) return;
    int m = mask[s];
    int r = m >> H_SHIFT;
    int c = m & H_MASK;
    int pos = atomicAdd(&g_offsets[r], 1);
    g_colsrt[pos] = (unsigned short)c;
#pragma unroll
    for (int e = 0; e < E_NUM; e++)
        g_wsrt[e * NS_NUM + pos] = g_weighted[e * NS_NUM + s];
}

// pack: per expert pair k=(e0,e1), one 8B record per CSR entry {w0h, w1h, col}
__global__ __launch_bounds__(256) void pack_kernel() {
    int idx = blockIdx.x * 256 + threadIdx.x;   // 64 * NS_NUM / 1
    int k = idx >> 14;                          // pair index
    int p = idx & (NS_NUM - 1);                 // entry index
    int e0 = k >> 3, e1 = k & 7;
    __half h0 = __float2half_rn(g_wsrt[e0 * NS_NUM + p]);
    __half h1 = __float2half_rn(g_wsrt[e1 * NS_NUM + p]);
    unsigned lo = (unsigned)__half_as_ushort(h0) | ((unsigned)__half_as_ushort(h1) << 16);
    unsigned hi = (unsigned)g_colsrt[p];
    g_pk[idx] = make_uint2(lo, hi);
}

// pair grouping: padded (to 4) exclusive scan over the 64 (e0,e1) pair counts
__global__ void pair_scan_kernel() {
    __shared__ int ptr[65];
    int tid = threadIdx.x;
    if (tid == 0) {
        int run = 0;
        for (int k = 0; k < 64; k++) {
            ptr[k] = run;
            run += ((g_paircnt[k] + 3) >> 2) << 2;
        }
        ptr[64] = run;
        g_total_blocks = run >> 2;
    }
    __syncthreads();
    for (int i = tid; i < 64; i += 256) g_pairoff[i] = ptr[i];
    for (int i = tid; i < PADMAX; i += 256) g_tokord[i] = -1;
    for (int k = tid; k < 64; k += 256) {
        int b0 = ptr[k] >> 2, b1 = ptr[k + 1] >> 2;
        for (int b = b0; b < b1; b++) g_blkpair[b] = k;
    }
}
__global__ void pair_scatter_kernel() {
    int t = blockIdx.x * blockDim.x + threadIdx.x;
    if (t >= T_TOK) return;
    int key = g_e0[t] * 8 + g_e1[t];
    int pos = atomicAdd(&g_pairoff[key], 1);
    g_tokord[pos] = t;
}

// ---------------- weighted: single pass over atoms, all 8 experts ----------------
__global__ __launch_bounds__(256) void weighted_kernel(
    const float* __restrict__ eaw, const float* __restrict__ atoms,
    const float* __restrict__ importance)
{
    __shared__ float wsm[E_NUM][A_NUM];
    int tid = threadIdx.x;
    int w = tid >> 5, lane = tid & 31;
    {
        float v0 = eaw[w * A_NUM + lane];
        float v1 = eaw[w * A_NUM + 32 + lane];
        float mx = fmaxf(v0, v1);
#pragma unroll
        for (int o = 16; o; o >>= 1) mx = fmaxf(mx, __shfl_xor_sync(0xffffffffu, mx, o));
        float e0 = expf(v0 - mx), e1 = expf(v1 - mx);
        float sm = e0 + e1;
#pragma unroll
        for (int o = 16; o; o >>= 1) sm += __shfl_xor_sync(0xffffffffu, sm, o);
        float inv = 1.f / sm;
        wsm[w][lane]      = e0 * inv;
        wsm[w][lane + 32] = e1 * inv;
    }
    __syncthreads();

    int s = blockIdx.x * 256 + tid;
    float acc[E_NUM];
#pragma unroll
    for (int e = 0; e < E_NUM; e++) acc[e] = 0.f;
#pragma unroll 4
    for (int a = 0; a < A_NUM; a++) {
        float va = atoms[a * NS_NUM + s];
#pragma unroll
        for (int e = 0; e < E_NUM; e++) acc[e] += wsm[e][a] * va;
    }
#pragma unroll
    for (int e = 0; e < E_NUM; e++) {
        float imp = importance[e * NS_NUM + s];
        g_weighted[e * NS_NUM + s] = acc[e] * (1.f / (1.f + expf(-imp)));
    }
}

// ---------------- gating: smem-free, warp-per-token ----------------
__global__ __launch_bounds__(256) void gate_kernel(
    const float* __restrict__ x, const float* __restrict__ gw)
{
    int t = blockIdx.x * 8 + (threadIdx.x >> 5);
    int lane = threadIdx.x & 31;
    const float4* xp = (const float4*)(x + (size_t)t * H_DIM);
    const float4* gp = (const float4*)gw;

    float acc[E_NUM];
#pragma unroll
    for (int e = 0; e < E_NUM; e++) acc[e] = 0.f;
#pragma unroll 4
    for (int i = 0; i < 16; i++) {
        float4 v = xp[lane + i * 32];
#pragma unroll
        for (int e = 0; e < E_NUM; e++) {
            float4 g = __ldg(&gp[e * 512 + lane + i * 32]);
            acc[e] += v.x * g.x + v.y * g.y + v.z * g.z + v.w * g.w;
        }
    }
#pragma unroll
    for (int e = 0; e < E_NUM; e++)
#pragma unroll
        for (int o = 16; o; o >>= 1)
            acc[e] += __shfl_xor_sync(0xffffffffu, acc[e], o);

    if (lane == 0) {
        float v[E_NUM];
#pragma unroll
        for (int e = 0; e < E_NUM; e++) v[e] = fminf(50.f, fmaxf(-50.f, acc[e]));
        int i0 = 0;
#pragma unroll
        for (int e = 1; e < E_NUM; e++) if (v[e] > v[i0]) i0 = e;
        int i1 = (i0 == 0) ? 1 : 0;
#pragma unroll
        for (int e = 0; e < E_NUM; e++) if (e != i0 && v[e] > v[i1]) i1 = e;
        float d = expf(v[i1] - v[i0]);
        float inv = 1.f / (1.f + d);
        g_e0[t] = i0; g_e1[t] = i1;
        g_rw0[t] = inv; g_rw1[t] = d * inv;
        atomicAdd(&g_paircnt[i0 * 8 + i1], 1);
    }
}

// ---------------- sparse contrib v9: sparse4 + packed 8B entry records ----------------
#define PLANE    2056
#define SP9_SMEM (4 * PLANE * 4 + 64)

__global__ __launch_bounds__(256, 4) void sparse9_kernel(
    const float* __restrict__ x, float* __restrict__ out)
{
    extern __shared__ char sm9[];
    float* xs  = (float*)sm9;                 // 4 planes of PLANE floats
    float* r0s = (float*)(sm9 + 4 * PLANE * 4);
    int*   tks = (int*)(r0s + 4);

    int b = blockIdx.x;
    if (b >= g_total_blocks) return;
    int pair = g_blkpair[b];
    const uint2* pk = g_pk + (size_t)pair * NS_NUM;
    int tid = threadIdx.x;

    if (tid < 4) {
        int tok = g_tokord[b * 4 + tid];
        tks[tid] = tok;
        r0s[tid] = tok >= 0 ? g_rw0[tok] : 0.f;
    }
    __syncthreads();

    int tk[4]; float r0v[4];
#pragma unroll
    for (int t = 0; t < 4; t++) { tk[t] = tks[t]; r0v[t] = r0s[t]; }

    // stage x rows into planes (coalesced, conflict-free)
#pragma unroll 1
    for (int t = 0; t < 4; t++) {
        float* pl = xs + t * PLANE;
        if (tk[t] >= 0) {
            const float* xp = x + (size_t)tk[t] * H_DIM;
            for (int i = tid; i < H_DIM; i += 256) pl[i] = xp[i];
        } else {
            for (int i = tid; i < H_DIM; i += 256) pl[i] = 0.f;
        }
    }
    __syncthreads();

    float acc[8][4];
#pragma unroll
    for (int rr = 0; rr < 8; rr++)
#pragma unroll
        for (int t = 0; t < 4; t++) acc[rr][t] = 0.f;

#pragma unroll 1
    for (int rr = 0; rr < 8; rr++) {
        int row = tid + rr * 256;              // adjacent lanes -> adjacent rows
        int p    = g_rowptr[row];
        int pend = g_rowptr[row + 1];
#pragma unroll 4
        for (; p < pend; p++) {
            uint2 rec = __ldg(pk + p);         // one 8B load per entry
            __half2 wh = *(__half2*)&rec.x;
            float w0p = __half2float(__low2half(wh));
            float w1p = __half2float(__high2half(wh));
            int cidx = (int)rec.y;
            float dd = w0p - w1p;
#pragma unroll
            for (int t = 0; t < 4; t++) {
                float comb = fmaf(r0v[t], dd, w1p);     // r0*w0 + (1-r0)*w1
                acc[rr][t] = fmaf(xs[t * PLANE + cidx], comb, acc[rr][t]);
            }
        }
    }

    // direct add into out (GEMM result already there; ordered via gemm_done event)
#pragma unroll 1
    for (int t = 0; t < 4; t++) {
        if (tk[t] < 0) continue;
        float* op = out + (size_t)tk[t] * H_DIM;
#pragma unroll
        for (int rr = 0; rr < 8; rr++) {
            int row = tid + rr * 256;
            op[row] += acc[rr][t];
        }
    }
}

// ---------------- launch ----------------
extern "C" void kernel_launch(void* const* d_in, const int* in_sizes, int n_in,
                              void* d_out, int out_size)
{
    const float* x     = (const float*)d_in[0];
    const float* gw    = (const float*)d_in[1];
    const float* W     = (const float*)d_in[2];
    const float* atoms = (const float*)d_in[3];
    const float* eaw   = (const float*)d_in[4];
    const float* imp   = (const float*)d_in[5];
    const int*   mask  = (const int*)d_in[6];
    float* out = (float*)d_out;

    (void)in_sizes; (void)n_in; (void)out_size;

    void *xh_p = nullptr, *wh_p = nullptr;
    cudaGetSymbolAddress(&xh_p, g_xh);
    cudaGetSymbolAddress(&wh_p, g_wh);

    cudaFuncSetAttribute(mma_gemm_kernel,
                         cudaFuncAttributeMaxDynamicSharedMemorySize, SMEM_MMA);

    cudaStream_t sd = g_fork_res.side;

    cudaEventRecord(g_fork_res.fork, 0);
    cudaStreamWaitEvent(sd, g_fork_res.fork, 0);

    // launches 1,2: fp16 converts (main)
    convert_fp16_kernel<<<(T_TOK * H_DIM / 2) / 256, 256>>>(x, (__half*)xh_p);
    convert_fp16_kernel<<<(H_DIM * H_DIM / 2) / 256, 256>>>(W, (__half*)wh_p);
    // launch 3: zero (side)
    zero_kernel<<<2, 1024, 0, sd>>>();
    // launch 4: GEMM (main) — profiled slot
    mma_gemm_kernel<<<dim3(H_DIM / BN, T_TOK / BM), 512, SMEM_MMA>>>(
        (const __half*)xh_p, (const __half*)wh_p, out);
    cudaEventRecord(g_fork_res.gemm_done, 0);

    // side branch: sparse prep (incl. pack) overlaps GEMM; sparse9 waits then adds into out
    hist_kernel<<<NS_NUM / 1024, 1024, 0, sd>>>(mask);
    weighted_kernel<<<NS_NUM / 256, 256, 0, sd>>>(eaw, atoms, imp);
    gate_kernel<<<T_TOK / 8, 256, 0, sd>>>(x, gw);
    scan_kernel<<<1, 256, 0, sd>>>();
    pair_scan_kernel<<<1, 256, 0, sd>>>();
    pair_scatter_kernel<<<T_TOK / 256, 256, 0, sd>>>();
    scatter_kernel<<<NS_NUM / 1024, 1024, 0, sd>>>(mask);
    pack_kernel<<<64 * NS_NUM / 256, 256, 0, sd>>>();
    cudaStreamWaitEvent(sd, g_fork_res.gemm_done, 0);
    sparse9_kernel<<<MAXBLK, 256, SP9_SMEM, sd>>>(x, out);
    cudaEventRecord(g_fork_res.join, sd);

    // join side branch back into the capture-origin stream
    cudaStreamWaitEvent(0, g_fork_res.join, 0);
}

// round 16
// speedup vs baseline: 1.2784x; 1.0717x over previous
#include <cuda_runtime.h>
#include <cuda_fp16.h>
#include <math.h>

// Problem constants (fixed shapes: B=2,S=2048,H=2048,E=8,A=64,NS=16384)
#define T_TOK   4096
#define H_DIM   2048
#define E_NUM   8
#define A_NUM   64
#define NS_NUM  16384
#define H_SHIFT 11
#define H_MASK  2047
#define PADMAX  4608
#define MAXBLK  1152

// GEMM: C[T,H] = fp16(x) @ fp16(W)^T, K = 2048, fp32 accumulate
// 256 threads (R5 geometry), NSTG=3 -> 166KB smem, ~44k regs: leaves room for sparse4 co-residency
#define KC      2048
#define BM      128
#define BN      256
#define BK      64
#define NCH     (KC / BK)            // 32
#define LDSB    144                  // smem row stride bytes (64 fp16 + 16 pad)
#define ABYTES  (BM * LDSB)          // 18432
#define STAGEB  ((BM + BN) * LDSB)   // 55296
#define NSTG    3
#define SMEM_MMA (NSTG * STAGEB)     // 165888

// ---------------- device scratch (no allocations allowed) ----------------
__device__ __half         g_xh[(size_t)T_TOK * KC];     // 16MB fp16(x)
__device__ __half         g_wh[(size_t)H_DIM * KC];     // 8MB  fp16(W)
__device__ float          g_contrib[(size_t)T_TOK * H_DIM];  // 32MB sparse contrib
__device__ float          g_weighted[E_NUM * NS_NUM];
__device__ float          g_wsrt[E_NUM * NS_NUM];       // weighted, CSR entry order
__device__ unsigned short g_colsrt[NS_NUM];             // col per CSR entry
__device__ int            g_counts[H_DIM];
__device__ int            g_rowptr[H_DIM + 1];
__device__ int            g_offsets[H_DIM];
__device__ int            g_e0[T_TOK];
__device__ int            g_e1[T_TOK];
__device__ float          g_rw0[T_TOK];
__device__ float          g_rw1[T_TOK];
// pair grouping (4 tokens per block)
__device__ int            g_paircnt[64];
__device__ int            g_pairoff[64];
__device__ int            g_tokord[PADMAX];
__device__ int            g_blkpair[MAXBLK];
__device__ int            g_total_blocks;

// ---------------- static stream/event resources (created pre-checkpoint) ----------------
struct GraphForkResources {
    cudaStream_t side;
    cudaEvent_t  fork, join;
    GraphForkResources() {
        cudaStreamCreateWithFlags(&side, cudaStreamNonBlocking);
        cudaEventCreateWithFlags(&fork, cudaEventDisableTiming);
        cudaEventCreateWithFlags(&join, cudaEventDisableTiming);
    }
};
static GraphForkResources g_fork_res;

// ---------------- ptx helpers (compute_80-level, safe on compute_103) ----------------
__device__ __forceinline__ unsigned smem_u32(const void* p) {
    unsigned r;
    asm("{ .reg .u64 t; cvta.to.shared.u64 t, %1; cvt.u32.u64 %0, t; }" : "=r"(r) : "l"(p));
    return r;
}
__device__ __forceinline__ void cp16(unsigned dst, const void* src) {
    asm volatile("cp.async.cg.shared.global [%0], [%1], 16;\n" :: "r"(dst), "l"(src));
}
__device__ __forceinline__ void cp_commit() { asm volatile("cp.async.commit_group;\n" ::: "memory"); }
__device__ __forceinline__ void cp_wait1()  { asm volatile("cp.async.wait_group 1;\n" ::: "memory"); }
__device__ __forceinline__ void ldsm4(unsigned* r, unsigned addr) {
    asm volatile("ldmatrix.sync.aligned.m8n8.x4.shared.b16 {%0,%1,%2,%3}, [%4];"
                 : "=r"(r[0]), "=r"(r[1]), "=r"(r[2]), "=r"(r[3]) : "r"(addr));
}
__device__ __forceinline__ void mma16816(float* d, const unsigned* a, unsigned b0, unsigned b1) {
    asm volatile(
        "mma.sync.aligned.m16n8k16.row.col.f32.f16.f16.f32 "
        "{%0,%1,%2,%3}, {%4,%5,%6,%7}, {%8,%9}, {%0,%1,%2,%3};"
        : "+f"(d[0]), "+f"(d[1]), "+f"(d[2]), "+f"(d[3])
        : "r"(a[0]), "r"(a[1]), "r"(a[2]), "r"(a[3]), "r"(b0), "r"(b1));
}

// ---------------- fp16 conversion (x and W share row length 2048) ----------------
__global__ __launch_bounds__(256) void convert_fp16_kernel(
    const float* __restrict__ src, __half* __restrict__ dst)
{
    int idx2 = blockIdx.x * 256 + threadIdx.x;          // float2 index
    float2 v = *(const float2*)(src + (size_t)idx2 * 2);
    __half2 h; h.x = __float2half_rn(v.x); h.y = __float2half_rn(v.y);
    *(__half2*)(dst + (size_t)idx2 * 2) = h;
}

// ---------------- HMMA GEMM: out = Xh @ Wh^T ----------------
// 256 threads, 8 warps as 2(m) x 4(n); warp tile 64x64; 3-stage cp.async pipeline.
__global__ __launch_bounds__(256, 1) void mma_gemm_kernel(
    const __half* __restrict__ A,
    const __half* __restrict__ B,
    float* __restrict__ out)
{
    extern __shared__ __align__(128) char sm[];
    const unsigned smb = smem_u32(sm);
    const int tid  = threadIdx.x;
    const int wid  = tid >> 5, lane = tid & 31;
    const int wm   = wid & 1;          // 0..1 (m)
    const int wn   = wid >> 1;         // 0..3 (n)
    const int trow0 = blockIdx.y * BM;
    const int ncol0 = blockIdx.x * BN;

    const int slot = tid & 7;
    const int rr0  = tid >> 3;         // 0..31
    const __half* aP = A + (size_t)(trow0 + rr0) * KC + slot * 8;
    const __half* bP = B + (size_t)(ncol0 + rr0) * KC + slot * 8;
    const unsigned dBase = rr0 * LDSB + slot * 16;

    const unsigned lrow = lane & 15, lhalf = lane >> 4;
    const unsigned aBase = smb + (wm * 64 + lrow) * LDSB + lhalf * 16;
    const unsigned bBase = smb + ABYTES + (wn * 64 + lrow) * LDSB + lhalf * 16;

    float acc[4][8][4];
#pragma unroll
    for (int i = 0; i < 4; i++)
#pragma unroll
        for (int j = 0; j < 8; j++)
#pragma unroll
            for (int r = 0; r < 4; r++) acc[i][j][r] = 0.f;

    // prologue: chunks 0,1
#pragma unroll
    for (int c = 0; c < 2; c++) {
        unsigned d = smb + c * STAGEB + dBase;
        const __half* ap = aP + c * BK;
        const __half* bp = bP + c * BK;
#pragma unroll
        for (int i = 0; i < 4; i++) { cp16(d, ap); ap += 32 * KC; d += 32 * LDSB; }
#pragma unroll
        for (int i = 0; i < 8; i++) { cp16(d, bp); bp += 32 * KC; d += 32 * LDSB; }
        cp_commit();
    }

    for (int c = 0; c < NCH; c++) {
        cp_wait1();          // chunk c resident (<=1 group outstanding)
        __syncthreads();

        int m = c + 2;
        if (m < NCH) {
            int sld = m - (m / 3) * 3;
            unsigned d = smb + sld * STAGEB + dBase;
            const __half* ap = aP + m * BK;
            const __half* bp = bP + m * BK;
#pragma unroll
            for (int i = 0; i < 4; i++) { cp16(d, ap); ap += 32 * KC; d += 32 * LDSB; }
#pragma unroll
            for (int i = 0; i < 8; i++) { cp16(d, bp); bp += 32 * KC; d += 32 * LDSB; }
        }
        cp_commit();

        int s = c - (c / 3) * 3;
        unsigned soff = (unsigned)s * STAGEB;
#pragma unroll
        for (int ks = 0; ks < 4; ks++) {
            unsigned a[4][4], b[4][4];
#pragma unroll
            for (int mi = 0; mi < 4; mi++)
                ldsm4(a[mi], aBase + soff + mi * (16 * LDSB) + ks * 32);
#pragma unroll
            for (int nj = 0; nj < 4; nj++)
                ldsm4(b[nj], bBase + soff + nj * (16 * LDSB) + ks * 32);
#pragma unroll
            for (int mi = 0; mi < 4; mi++) {
#pragma unroll
                for (int nb = 0; nb < 4; nb++) {
                    mma16816(acc[mi][2*nb],   a[mi], b[nb][0], b[nb][2]);
                    mma16816(acc[mi][2*nb+1], a[mi], b[nb][1], b[nb][3]);
                }
            }
        }
    }

    const int r0 = trow0 + wm * 64 + (lane >> 2);
    const int cc = ncol0 + wn * 64 + (lane & 3) * 2;
#pragma unroll
    for (int mi = 0; mi < 4; mi++) {
#pragma unroll
        for (int ni = 0; ni < 8; ni++) {
            float* p0 = out + (size_t)(r0 + mi * 16) * H_DIM + cc + ni * 8;
            float* p1 = p0 + 8 * H_DIM;
            *(float2*)p0 = make_float2(acc[mi][ni][0], acc[mi][ni][1]);
            *(float2*)p1 = make_float2(acc[mi][ni][2], acc[mi][ni][3]);
        }
    }
}

// ---------------- final add: out += contrib ----------------
__global__ __launch_bounds__(256) void add_kernel(float* __restrict__ out) {
    size_t i = (size_t)blockIdx.x * 256 + threadIdx.x;
    float4* o = (float4*)out;
    const float4* c = (const float4*)g_contrib;
    float4 a = o[i], b = c[i];
    a.x += b.x; a.y += b.y; a.z += b.z; a.w += b.w;
    o[i] = a;
}

// ---------------- tiny setup kernels ----------------
__global__ void zero_kernel() {
    int i = blockIdx.x * 1024 + threadIdx.x;
    if (i < H_DIM) g_counts[i] = 0;
    if (i < 64)    g_paircnt[i] = 0;
}
__global__ void hist_kernel(const int* __restrict__ mask) {
    int s = blockIdx.x * blockDim.x + threadIdx.x;
    if (s < NS_NUM) atomicAdd(&g_counts[mask[s] >> H_SHIFT], 1);
}
__global__ void scan_kernel() {
    __shared__ int chunk[256];
    int tid = threadIdx.x;
    int base = tid * 8;
    int local[8]; int s = 0;
#pragma unroll
    for (int c = 0; c < 8; c++) { local[c] = g_counts[base + c]; s += local[c]; }
    chunk[tid] = s;
    __syncthreads();
    if (tid == 0) {
        int run = 0;
        for (int i = 0; i < 256; i++) { int t = chunk[i]; chunk[i] = run; run += t; }
        g_rowptr[H_DIM] = run;
    }
    __syncthreads();
    int run = chunk[tid];
#pragma unroll
    for (int c = 0; c < 8; c++) {
        g_rowptr[base + c]  = run;
        g_offsets[base + c] = run;
        run += local[c];
    }
}
__global__ void scatter_kernel(const int* __restrict__ mask) {
    int s = blockIdx.x * blockDim.x + threadIdx.x;
    if (s >= NS_NUM) return;
    int m = mask[s];
    int r = m >> H_SHIFT;
    int c = m & H_MASK;
    int pos = atomicAdd(&g_offsets[r], 1);
    g_colsrt[pos] = (unsigned short)c;
#pragma unroll
    for (int e = 0; e < E_NUM; e++)
        g_wsrt[e * NS_NUM + pos] = g_weighted[e * NS_NUM + s];
}

// pair grouping: padded (to 4) exclusive scan over the 64 (e0,e1) pair counts
__global__ void pair_scan_kernel() {
    __shared__ int ptr[65];
    int tid = threadIdx.x;
    if (tid == 0) {
        int run = 0;
        for (int k = 0; k < 64; k++) {
            ptr[k] = run;
            run += ((g_paircnt[k] + 3) >> 2) << 2;
        }
        ptr[64] = run;
        g_total_blocks = run >> 2;
    }
    __syncthreads();
    for (int i = tid; i < 64; i += 256) g_pairoff[i] = ptr[i];
    for (int i = tid; i < PADMAX; i += 256) g_tokord[i] = -1;
    for (int k = tid; k < 64; k += 256) {
        int b0 = ptr[k] >> 2, b1 = ptr[k + 1] >> 2;
        for (int b = b0; b < b1; b++) g_blkpair[b] = k;
    }
}
__global__ void pair_scatter_kernel() {
    int t = blockIdx.x * blockDim.x + threadIdx.x;
    if (t >= T_TOK) return;
    int key = g_e0[t] * 8 + g_e1[t];
    int pos = atomicAdd(&g_pairoff[key], 1);
    g_tokord[pos] = t;
}

// ---------------- weighted: single pass over atoms, all 8 experts ----------------
__global__ __launch_bounds__(256) void weighted_kernel(
    const float* __restrict__ eaw, const float* __restrict__ atoms,
    const float* __restrict__ importance)
{
    __shared__ float wsm[E_NUM][A_NUM];
    int tid = threadIdx.x;
    int w = tid >> 5, lane = tid & 31;
    {
        float v0 = eaw[w * A_NUM + lane];
        float v1 = eaw[w * A_NUM + 32 + lane];
        float mx = fmaxf(v0, v1);
#pragma unroll
        for (int o = 16; o; o >>= 1) mx = fmaxf(mx, __shfl_xor_sync(0xffffffffu, mx, o));
        float e0 = expf(v0 - mx), e1 = expf(v1 - mx);
        float sm = e0 + e1;
#pragma unroll
        for (int o = 16; o; o >>= 1) sm += __shfl_xor_sync(0xffffffffu, sm, o);
        float inv = 1.f / sm;
        wsm[w][lane]      = e0 * inv;
        wsm[w][lane + 32] = e1 * inv;
    }
    __syncthreads();

    int s = blockIdx.x * 256 + tid;
    float acc[E_NUM];
#pragma unroll
    for (int e = 0; e < E_NUM; e++) acc[e] = 0.f;
#pragma unroll 4
    for (int a = 0; a < A_NUM; a++) {
        float va = atoms[a * NS_NUM + s];
#pragma unroll
        for (int e = 0; e < E_NUM; e++) acc[e] += wsm[e][a] * va;
    }
#pragma unroll
    for (int e = 0; e < E_NUM; e++) {
        float imp = importance[e * NS_NUM + s];
        g_weighted[e * NS_NUM + s] = acc[e] * (1.f / (1.f + expf(-imp)));
    }
}

// ---------------- gating: smem-free, warp-per-token ----------------
__global__ __launch_bounds__(256) void gate_kernel(
    const float* __restrict__ x, const float* __restrict__ gw)
{
    int t = blockIdx.x * 8 + (threadIdx.x >> 5);
    int lane = threadIdx.x & 31;
    const float4* xp = (const float4*)(x + (size_t)t * H_DIM);
    const float4* gp = (const float4*)gw;

    float acc[E_NUM];
#pragma unroll
    for (int e = 0; e < E_NUM; e++) acc[e] = 0.f;
#pragma unroll 4
    for (int i = 0; i < 16; i++) {
        float4 v = xp[lane + i * 32];
#pragma unroll
        for (int e = 0; e < E_NUM; e++) {
            float4 g = __ldg(&gp[e * 512 + lane + i * 32]);
            acc[e] += v.x * g.x + v.y * g.y + v.z * g.z + v.w * g.w;
        }
    }
#pragma unroll
    for (int e = 0; e < E_NUM; e++)
#pragma unroll
        for (int o = 16; o; o >>= 1)
            acc[e] += __shfl_xor_sync(0xffffffffu, acc[e], o);

    if (lane == 0) {
        float v[E_NUM];
#pragma unroll
        for (int e = 0; e < E_NUM; e++) v[e] = fminf(50.f, fmaxf(-50.f, acc[e]));
        int i0 = 0;
#pragma unroll
        for (int e = 1; e < E_NUM; e++) if (v[e] > v[i0]) i0 = e;
        int i1 = (i0 == 0) ? 1 : 0;
#pragma unroll
        for (int e = 0; e < E_NUM; e++) if (e != i0 && v[e] > v[i1]) i1 = e;
        float d = expf(v[i1] - v[i0]);
        float inv = 1.f / (1.f + d);
        g_e0[t] = i0; g_e1[t] = i1;
        g_rw0[t] = inv; g_rw1[t] = d * inv;
        atomicAdd(&g_paircnt[i0 * 8 + i1], 1);
    }
}

// ---------------- sparse contrib v4c: sparse4 structure, writes contrib (no GEMM dep) ----------------
#define PLANE    2056
#define SP4_SMEM (4 * PLANE * 4 + 64)

__global__ __launch_bounds__(256, 4) void sparse4_kernel(
    const float* __restrict__ x)
{
    extern __shared__ char sm4[];
    float* xs  = (float*)sm4;                 // 4 planes of PLANE floats
    float* r0s = (float*)(sm4 + 4 * PLANE * 4);
    int*   tks = (int*)(r0s + 4);

    int b = blockIdx.x;
    if (b >= g_total_blocks) return;
    int pair = g_blkpair[b];
    const float* w0 = g_wsrt + (pair >> 3) * NS_NUM;
    const float* w1 = g_wsrt + (pair & 7) * NS_NUM;
    int tid = threadIdx.x;

    if (tid < 4) {
        int tok = g_tokord[b * 4 + tid];
        tks[tid] = tok;
        r0s[tid] = tok >= 0 ? g_rw0[tok] : 0.f;
    }
    __syncthreads();

    int tk[4]; float r0v[4];
#pragma unroll
    for (int t = 0; t < 4; t++) { tk[t] = tks[t]; r0v[t] = r0s[t]; }

    // stage x rows into planes (coalesced, conflict-free)
#pragma unroll 1
    for (int t = 0; t < 4; t++) {
        float* pl = xs + t * PLANE;
        if (tk[t] >= 0) {
            const float* xp = x + (size_t)tk[t] * H_DIM;
            for (int i = tid; i < H_DIM; i += 256) pl[i] = xp[i];
        } else {
            for (int i = tid; i < H_DIM; i += 256) pl[i] = 0.f;
        }
    }
    __syncthreads();

    float acc[8][4];
#pragma unroll
    for (int rr = 0; rr < 8; rr++)
#pragma unroll
        for (int t = 0; t < 4; t++) acc[rr][t] = 0.f;

#pragma unroll 1
    for (int rr = 0; rr < 8; rr++) {
        int row = tid + rr * 256;              // adjacent lanes -> adjacent rows
        int p    = g_rowptr[row];
        int pend = g_rowptr[row + 1];
#pragma unroll 4
        for (; p < pend; p++) {
            float w0p = __ldg(w0 + p);
            float w1p = __ldg(w1 + p);
            int cidx = (int)__ldg(g_colsrt + p);
            float dd = w0p - w1p;
#pragma unroll
            for (int t = 0; t < 4; t++) {
                float comb = fmaf(r0v[t], dd, w1p);     // r0*w0 + (1-r0)*w1
                acc[rr][t] = fmaf(xs[t * PLANE + cidx], comb, acc[rr][t]);
            }
        }
    }

    // write contrib (coalesced per (t, rr))
#pragma unroll 1
    for (int t = 0; t < 4; t++) {
        if (tk[t] < 0) continue;
        float* op = g_contrib + (size_t)tk[t] * H_DIM;
#pragma unroll
        for (int rr = 0; rr < 8; rr++) {
            int row = tid + rr * 256;
            op[row] = acc[rr][t];
        }
    }
}

// ---------------- launch ----------------
extern "C" void kernel_launch(void* const* d_in, const int* in_sizes, int n_in,
                              void* d_out, int out_size)
{
    const float* x     = (const float*)d_in[0];
    const float* gw    = (const float*)d_in[1];
    const float* W     = (const float*)d_in[2];
    const float* atoms = (const float*)d_in[3];
    const float* eaw   = (const float*)d_in[4];
    const float* imp   = (const float*)d_in[5];
    const int*   mask  = (const int*)d_in[6];
    float* out = (float*)d_out;

    (void)in_sizes; (void)n_in; (void)out_size;

    void *xh_p = nullptr, *wh_p = nullptr;
    cudaGetSymbolAddress(&xh_p, g_xh);
    cudaGetSymbolAddress(&wh_p, g_wh);

    cudaFuncSetAttribute(mma_gemm_kernel,
                         cudaFuncAttributeMaxDynamicSharedMemorySize, SMEM_MMA);

    cudaStream_t sd = g_fork_res.side;

    cudaEventRecord(g_fork_res.fork, 0);
    cudaStreamWaitEvent(sd, g_fork_res.fork, 0);

    // launches 1,2: fp16 converts (main)
    convert_fp16_kernel<<<(T_TOK * H_DIM / 2) / 256, 256>>>(x, (__half*)xh_p);
    convert_fp16_kernel<<<(H_DIM * H_DIM / 2) / 256, 256>>>(W, (__half*)wh_p);
    // launch 3: zero (side)
    zero_kernel<<<2, 1024, 0, sd>>>();
    // launch 4: GEMM (main) — profiled slot; 166KB smem + 44k regs leaves room for sparse4
    mma_gemm_kernel<<<dim3(H_DIM / BN, T_TOK / BM), 256, SMEM_MMA>>>(
        (const __half*)xh_p, (const __half*)wh_p, out);

    // side branch: sparse prep, then sparse4 co-runs with GEMM (writes contrib; no GEMM dep)
    hist_kernel<<<NS_NUM / 1024, 1024, 0, sd>>>(mask);
    weighted_kernel<<<NS_NUM / 256, 256, 0, sd>>>(eaw, atoms, imp);
    gate_kernel<<<T_TOK / 8, 256, 0, sd>>>(x, gw);
    scan_kernel<<<1, 256, 0, sd>>>();
    pair_scan_kernel<<<1, 256, 0, sd>>>();
    pair_scatter_kernel<<<T_TOK / 256, 256, 0, sd>>>();
    scatter_kernel<<<NS_NUM / 1024, 1024, 0, sd>>>(mask);
    sparse4_kernel<<<MAXBLK, 256, SP4_SMEM, sd>>>(x);
    cudaEventRecord(g_fork_res.join, sd);

    // join, then out += contrib
    cudaStreamWaitEvent(0, g_fork_res.join, 0);
    add_kernel<<<(T_TOK * H_DIM / 4) / 256, 256>>>(out);
}

// round 17
// speedup vs baseline: 1.2904x; 1.0094x over previous
#include <cuda_runtime.h>
#include <cuda_fp16.h>
#include <math.h>

// Problem constants (fixed shapes: B=2,S=2048,H=2048,E=8,A=64,NS=16384)
#define T_TOK   4096
#define H_DIM   2048
#define E_NUM   8
#define A_NUM   64
#define NS_NUM  16384
#define H_SHIFT 11
#define H_MASK  2047
#define PADMAX  4608
#define MAXBLK  576

// GEMM: C[T,H] = fp16(x) @ fp16(W)^T, K = 2048, fp32 accumulate
// 256 threads, NSTG=3 -> 166KB smem, ~44k regs: leaves room for sparse co-residency
#define KC      2048
#define BM      128
#define BN      256
#define BK      64
#define NCH     (KC / BK)            // 32
#define LDSB    144                  // smem row stride bytes (64 fp16 + 16 pad)
#define ABYTES  (BM * LDSB)          // 18432
#define STAGEB  ((BM + BN) * LDSB)   // 55296
#define NSTG    3
#define SMEM_MMA (NSTG * STAGEB)     // 165888

// ---------------- device scratch (no allocations allowed) ----------------
__device__ __half         g_xh[(size_t)T_TOK * KC];     // 16MB fp16(x)
__device__ __half         g_wh[(size_t)H_DIM * KC];     // 8MB  fp16(W)
__device__ float          g_contrib[(size_t)T_TOK * H_DIM];  // 32MB sparse contrib
__device__ float          g_weighted[E_NUM * NS_NUM];
__device__ float          g_wsrt[E_NUM * NS_NUM];       // weighted, CSR entry order
__device__ unsigned short g_colsrt[NS_NUM];             // col per CSR entry
__device__ int            g_counts[H_DIM];
__device__ int            g_rowptr[H_DIM + 1];
__device__ int            g_offsets[H_DIM];
__device__ int            g_e0[T_TOK];
__device__ int            g_e1[T_TOK];
__device__ float          g_rw0[T_TOK];
__device__ float          g_rw1[T_TOK];
// pair grouping (8 tokens per block)
__device__ int            g_paircnt[64];
__device__ int            g_pairoff[64];
__device__ int            g_tokord[PADMAX];
__device__ int            g_blkpair[MAXBLK];
__device__ int            g_total_blocks;

// ---------------- static stream/event resources (created pre-checkpoint) ----------------
struct GraphForkResources {
    cudaStream_t side;
    cudaEvent_t  fork, join;
    GraphForkResources() {
        cudaStreamCreateWithFlags(&side, cudaStreamNonBlocking);
        cudaEventCreateWithFlags(&fork, cudaEventDisableTiming);
        cudaEventCreateWithFlags(&join, cudaEventDisableTiming);
    }
};
static GraphForkResources g_fork_res;

// ---------------- ptx helpers (compute_80-level, safe on compute_103) ----------------
__device__ __forceinline__ unsigned smem_u32(const void* p) {
    unsigned r;
    asm("{ .reg .u64 t; cvta.to.shared.u64 t, %1; cvt.u32.u64 %0, t; }" : "=r"(r) : "l"(p));
    return r;
}
__device__ __forceinline__ void cp16(unsigned dst, const void* src) {
    asm volatile("cp.async.cg.shared.global [%0], [%1], 16;\n" :: "r"(dst), "l"(src));
}
__device__ __forceinline__ void cp_commit() { asm volatile("cp.async.commit_group;\n" ::: "memory"); }
__device__ __forceinline__ void cp_wait1()  { asm volatile("cp.async.wait_group 1;\n" ::: "memory"); }
__device__ __forceinline__ void ldsm4(unsigned* r, unsigned addr) {
    asm volatile("ldmatrix.sync.aligned.m8n8.x4.shared.b16 {%0,%1,%2,%3}, [%4];"
                 : "=r"(r[0]), "=r"(r[1]), "=r"(r[2]), "=r"(r[3]) : "r"(addr));
}
__device__ __forceinline__ void mma16816(float* d, const unsigned* a, unsigned b0, unsigned b1) {
    asm volatile(
        "mma.sync.aligned.m16n8k16.row.col.f32.f16.f16.f32 "
        "{%0,%1,%2,%3}, {%4,%5,%6,%7}, {%8,%9}, {%0,%1,%2,%3};"
        : "+f"(d[0]), "+f"(d[1]), "+f"(d[2]), "+f"(d[3])
        : "r"(a[0]), "r"(a[1]), "r"(a[2]), "r"(a[3]), "r"(b0), "r"(b1));
}

// ---------------- fp16 conversion (x and W share row length 2048) ----------------
__global__ __launch_bounds__(256) void convert_fp16_kernel(
    const float* __restrict__ src, __half* __restrict__ dst)
{
    int idx2 = blockIdx.x * 256 + threadIdx.x;          // float2 index
    float2 v = *(const float2*)(src + (size_t)idx2 * 2);
    __half2 h; h.x = __float2half_rn(v.x); h.y = __float2half_rn(v.y);
    *(__half2*)(dst + (size_t)idx2 * 2) = h;
}

// ---------------- HMMA GEMM: out = Xh @ Wh^T ----------------
// 256 threads, 8 warps as 2(m) x 4(n); warp tile 64x64; 3-stage cp.async pipeline.
__global__ __launch_bounds__(256, 1) void mma_gemm_kernel(
    const __half* __restrict__ A,
    const __half* __restrict__ B,
    float* __restrict__ out)
{
    extern __shared__ __align__(128) char sm[];
    const unsigned smb = smem_u32(sm);
    const int tid  = threadIdx.x;
    const int wid  = tid >> 5, lane = tid & 31;
    const int wm   = wid & 1;          // 0..1 (m)
    const int wn   = wid >> 1;         // 0..3 (n)
    const int trow0 = blockIdx.y * BM;
    const int ncol0 = blockIdx.x * BN;

    const int slot = tid & 7;
    const int rr0  = tid >> 3;         // 0..31
    const __half* aP = A + (size_t)(trow0 + rr0) * KC + slot * 8;
    const __half* bP = B + (size_t)(ncol0 + rr0) * KC + slot * 8;
    const unsigned dBase = rr0 * LDSB + slot * 16;

    const unsigned lrow = lane & 15, lhalf = lane >> 4;
    const unsigned aBase = smb + (wm * 64 + lrow) * LDSB + lhalf * 16;
    const unsigned bBase = smb + ABYTES + (wn * 64 + lrow) * LDSB + lhalf * 16;

    float acc[4][8][4];
#pragma unroll
    for (int i = 0; i < 4; i++)
#pragma unroll
        for (int j = 0; j < 8; j++)
#pragma unroll
            for (int r = 0; r < 4; r++) acc[i][j][r] = 0.f;

    // prologue: chunks 0,1
#pragma unroll
    for (int c = 0; c < 2; c++) {
        unsigned d = smb + c * STAGEB + dBase;
        const __half* ap = aP + c * BK;
        const __half* bp = bP + c * BK;
#pragma unroll
        for (int i = 0; i < 4; i++) { cp16(d, ap); ap += 32 * KC; d += 32 * LDSB; }
#pragma unroll
        for (int i = 0; i < 8; i++) { cp16(d, bp); bp += 32 * KC; d += 32 * LDSB; }
        cp_commit();
    }

    for (int c = 0; c < NCH; c++) {
        cp_wait1();          // chunk c resident (<=1 group outstanding)
        __syncthreads();

        int m = c + 2;
        if (m < NCH) {
            int sld = m - (m / 3) * 3;
            unsigned d = smb + sld * STAGEB + dBase;
            const __half* ap = aP + m * BK;
            const __half* bp = bP + m * BK;
#pragma unroll
            for (int i = 0; i < 4; i++) { cp16(d, ap); ap += 32 * KC; d += 32 * LDSB; }
#pragma unroll
            for (int i = 0; i < 8; i++) { cp16(d, bp); bp += 32 * KC; d += 32 * LDSB; }
        }
        cp_commit();

        int s = c - (c / 3) * 3;
        unsigned soff = (unsigned)s * STAGEB;
#pragma unroll
        for (int ks = 0; ks < 4; ks++) {
            unsigned a[4][4], b[4][4];
#pragma unroll
            for (int mi = 0; mi < 4; mi++)
                ldsm4(a[mi], aBase + soff + mi * (16 * LDSB) + ks * 32);
#pragma unroll
            for (int nj = 0; nj < 4; nj++)
                ldsm4(b[nj], bBase + soff + nj * (16 * LDSB) + ks * 32);
#pragma unroll
            for (int mi = 0; mi < 4; mi++) {
#pragma unroll
                for (int nb = 0; nb < 4; nb++) {
                    mma16816(acc[mi][2*nb],   a[mi], b[nb][0], b[nb][2]);
                    mma16816(acc[mi][2*nb+1], a[mi], b[nb][1], b[nb][3]);
                }
            }
        }
    }

    const int r0 = trow0 + wm * 64 + (lane >> 2);
    const int cc = ncol0 + wn * 64 + (lane & 3) * 2;
#pragma unroll
    for (int mi = 0; mi < 4; mi++) {
#pragma unroll
        for (int ni = 0; ni < 8; ni++) {
            float* p0 = out + (size_t)(r0 + mi * 16) * H_DIM + cc + ni * 8;
            float* p1 = p0 + 8 * H_DIM;
            *(float2*)p0 = make_float2(acc[mi][ni][0], acc[mi][ni][1]);
            *(float2*)p1 = make_float2(acc[mi][ni][2], acc[mi][ni][3]);
        }
    }
}

// ---------------- final add: out += contrib ----------------
__global__ __launch_bounds__(256) void add_kernel(float* __restrict__ out) {
    size_t i = (size_t)blockIdx.x * 256 + threadIdx.x;
    float4* o = (float4*)out;
    const float4* c = (const float4*)g_contrib;
    float4 a = o[i], b = c[i];
    a.x += b.x; a.y += b.y; a.z += b.z; a.w += b.w;
    o[i] = a;
}

// ---------------- tiny setup kernels ----------------
__global__ void zero_kernel() {
    int i = blockIdx.x * 1024 + threadIdx.x;
    if (i < H_DIM) g_counts[i] = 0;
    if (i < 64)    g_paircnt[i] = 0;
}
__global__ void hist_kernel(const int* __restrict__ mask) {
    int s = blockIdx.x * blockDim.x + threadIdx.x;
    if (s < NS_NUM) atomicAdd(&g_counts[mask[s] >> H_SHIFT], 1);
}
__global__ void scan_kernel() {
    __shared__ int chunk[256];
    int tid = threadIdx.x;
    int base = tid * 8;
    int local[8]; int s = 0;
#pragma unroll
    for (int c = 0; c < 8; c++) { local[c] = g_counts[base + c]; s += local[c]; }
    chunk[tid] = s;
    __syncthreads();
    if (tid == 0) {
        int run = 0;
        for (int i = 0; i < 256; i++) { int t = chunk[i]; chunk[i] = run; run += t; }
        g_rowptr[H_DIM] = run;
    }
    __syncthreads();
    int run = chunk[tid];
#pragma unroll
    for (int c = 0; c < 8; c++) {
        g_rowptr[base + c]  = run;
        g_offsets[base + c] = run;
        run += local[c];
    }
}
__global__ void scatter_kernel(const int* __restrict__ mask) {
    int s = blockIdx.x * blockDim.x + threadIdx.x;
    if (s >= NS_NUM) return;
    int m = mask[s];
    int r = m >> H_SHIFT;
    int c = m & H_MASK;
    int pos = atomicAdd(&g_offsets[r], 1);
    g_colsrt[pos] = (unsigned short)c;
#pragma unroll
    for (int e = 0; e < E_NUM; e++)
        g_wsrt[e * NS_NUM + pos] = g_weighted[e * NS_NUM + s];
}

// pair grouping: padded (to 8) exclusive scan over the 64 (e0,e1) pair counts
__global__ void pair_scan_kernel() {
    __shared__ int ptr[65];
    int tid = threadIdx.x;
    if (tid == 0) {
        int run = 0;
        for (int k = 0; k < 64; k++) {
            ptr[k] = run;
            run += ((g_paircnt[k] + 7) >> 3) << 3;
        }
        ptr[64] = run;
        g_total_blocks = run >> 3;
    }
    __syncthreads();
    for (int i = tid; i < 64; i += 256) g_pairoff[i] = ptr[i];
    for (int i = tid; i < PADMAX; i += 256) g_tokord[i] = -1;
    for (int k = tid; k < 64; k += 256) {
        int b0 = ptr[k] >> 3, b1 = ptr[k + 1] >> 3;
        for (int b = b0; b < b1; b++) g_blkpair[b] = k;
    }
}
__global__ void pair_scatter_kernel() {
    int t = blockIdx.x * blockDim.x + threadIdx.x;
    if (t >= T_TOK) return;
    int key = g_e0[t] * 8 + g_e1[t];
    int pos = atomicAdd(&g_pairoff[key], 1);
    g_tokord[pos] = t;
}

// ---------------- weighted: single pass over atoms, all 8 experts ----------------
__global__ __launch_bounds__(256) void weighted_kernel(
    const float* __restrict__ eaw, const float* __restrict__ atoms,
    const float* __restrict__ importance)
{
    __shared__ float wsm[E_NUM][A_NUM];
    int tid = threadIdx.x;
    int w = tid >> 5, lane = tid & 31;
    {
        float v0 = eaw[w * A_NUM + lane];
        float v1 = eaw[w * A_NUM + 32 + lane];
        float mx = fmaxf(v0, v1);
#pragma unroll
        for (int o = 16; o; o >>= 1) mx = fmaxf(mx, __shfl_xor_sync(0xffffffffu, mx, o));
        float e0 = expf(v0 - mx), e1 = expf(v1 - mx);
        float sm = e0 + e1;
#pragma unroll
        for (int o = 16; o; o >>= 1) sm += __shfl_xor_sync(0xffffffffu, sm, o);
        float inv = 1.f / sm;
        wsm[w][lane]      = e0 * inv;
        wsm[w][lane + 32] = e1 * inv;
    }
    __syncthreads();

    int s = blockIdx.x * 256 + tid;
    float acc[E_NUM];
#pragma unroll
    for (int e = 0; e < E_NUM; e++) acc[e] = 0.f;
#pragma unroll 4
    for (int a = 0; a < A_NUM; a++) {
        float va = atoms[a * NS_NUM + s];
#pragma unroll
        for (int e = 0; e < E_NUM; e++) acc[e] += wsm[e][a] * va;
    }
#pragma unroll
    for (int e = 0; e < E_NUM; e++) {
        float imp = importance[e * NS_NUM + s];
        g_weighted[e * NS_NUM + s] = acc[e] * (1.f / (1.f + expf(-imp)));
    }
}

// ---------------- gating: smem-free, warp-per-token ----------------
__global__ __launch_bounds__(256) void gate_kernel(
    const float* __restrict__ x, const float* __restrict__ gw)
{
    int t = blockIdx.x * 8 + (threadIdx.x >> 5);
    int lane = threadIdx.x & 31;
    const float4* xp = (const float4*)(x + (size_t)t * H_DIM);
    const float4* gp = (const float4*)gw;

    float acc[E_NUM];
#pragma unroll
    for (int e = 0; e < E_NUM; e++) acc[e] = 0.f;
#pragma unroll 4
    for (int i = 0; i < 16; i++) {
        float4 v = xp[lane + i * 32];
#pragma unroll
        for (int e = 0; e < E_NUM; e++) {
            float4 g = __ldg(&gp[e * 512 + lane + i * 32]);
            acc[e] += v.x * g.x + v.y * g.y + v.z * g.z + v.w * g.w;
        }
    }
#pragma unroll
    for (int e = 0; e < E_NUM; e++)
#pragma unroll
        for (int o = 16; o; o >>= 1)
            acc[e] += __shfl_xor_sync(0xffffffffu, acc[e], o);

    if (lane == 0) {
        float v[E_NUM];
#pragma unroll
        for (int e = 0; e < E_NUM; e++) v[e] = fminf(50.f, fmaxf(-50.f, acc[e]));
        int i0 = 0;
#pragma unroll
        for (int e = 1; e < E_NUM; e++) if (v[e] > v[i0]) i0 = e;
        int i1 = (i0 == 0) ? 1 : 0;
#pragma unroll
        for (int e = 0; e < E_NUM; e++) if (e != i0 && v[e] > v[i1]) i1 = e;
        float d = expf(v[i1] - v[i0]);
        float inv = 1.f / (1.f + d);
        g_e0[t] = i0; g_e1[t] = i1;
        g_rw0[t] = inv; g_rw1[t] = d * inv;
        atomicAdd(&g_paircnt[i0 * 8 + i1], 1);
    }
}

// ---------------- sparse contrib v10: 8 tokens/block via half2 planes, 512 thr, 2 blk/SM ----------------
// smem: 4 half2-planes (token pairs) of PLANE2 half2 = ~33KB; 1024 thr/SM, half the blocks of sparse4
#define PLANE2   2056
#define SP10_SMEM (4 * PLANE2 * 4 + 64)

__global__ __launch_bounds__(512, 2) void sparse10_kernel(float* __restrict__ contrib)
{
    extern __shared__ char sm10[];
    __half2* xs = (__half2*)sm10;             // 4 planes of PLANE2 half2
    float* r0s  = (float*)(sm10 + 4 * PLANE2 * 4);
    int*   tks  = (int*)(r0s + 8);

    int b = blockIdx.x;
    if (b >= g_total_blocks) return;
    int pair = g_blkpair[b];
    const float* w0 = g_wsrt + (pair >> 3) * NS_NUM;
    const float* w1 = g_wsrt + (pair & 7) * NS_NUM;
    int tid = threadIdx.x;

    if (tid < 8) {
        int tok = g_tokord[b * 8 + tid];
        tks[tid] = tok;
        r0s[tid] = tok >= 0 ? g_rw0[tok] : 0.f;
    }
    __syncthreads();

    float r0v[8];
#pragma unroll
    for (int t = 0; t < 8; t++) r0v[t] = r0s[t];

    // stage token pairs into half2 planes (reads pre-converted g_xh)
#pragma unroll 1
    for (int j = 0; j < 4; j++) {
        int t0 = tks[2 * j], t1 = tks[2 * j + 1];
        const __half* p0 = g_xh + (size_t)(t0 < 0 ? 0 : t0) * KC;
        const __half* p1 = g_xh + (size_t)(t1 < 0 ? 0 : t1) * KC;
        __half z = __float2half_rn(0.f);
        __half2* pl = xs + j * PLANE2;
        for (int i = tid; i < H_DIM; i += 512) {
            __half a = (t0 >= 0) ? p0[i] : z;
            __half bb = (t1 >= 0) ? p1[i] : z;
            pl[i] = __halves2half2(a, bb);
        }
    }
    __syncthreads();

    float acc[4][8];
#pragma unroll
    for (int rr = 0; rr < 4; rr++)
#pragma unroll
        for (int t = 0; t < 8; t++) acc[rr][t] = 0.f;

#pragma unroll 1
    for (int rr = 0; rr < 4; rr++) {
        int row = tid + rr * 512;              // adjacent lanes -> adjacent rows
        int p    = g_rowptr[row];
        int pend = g_rowptr[row + 1];
#pragma unroll 4
        for (; p < pend; p++) {
            float w0p = __ldg(w0 + p);
            float w1p = __ldg(w1 + p);
            int cidx = (int)__ldg(g_colsrt + p);
            float dd = w0p - w1p;
#pragma unroll
            for (int j = 0; j < 4; j++) {
                float2 xf = __half22float2(xs[j * PLANE2 + cidx]);
                float c0 = fmaf(r0v[2*j],   dd, w1p);   // r0*w0 + (1-r0)*w1
                float c1 = fmaf(r0v[2*j+1], dd, w1p);
                acc[rr][2*j]   = fmaf(xf.x, c0, acc[rr][2*j]);
                acc[rr][2*j+1] = fmaf(xf.y, c1, acc[rr][2*j+1]);
            }
        }
    }

    // write contrib (coalesced per (t, rr))
#pragma unroll 1
    for (int t = 0; t < 8; t++) {
        int tok = tks[t];
        if (tok < 0) continue;
        float* op = contrib + (size_t)tok * H_DIM;
#pragma unroll
        for (int rr = 0; rr < 4; rr++) {
            int row = tid + rr * 512;
            op[row] = acc[rr][t];
        }
    }
}

// ---------------- launch ----------------
extern "C" void kernel_launch(void* const* d_in, const int* in_sizes, int n_in,
                              void* d_out, int out_size)
{
    const float* x     = (const float*)d_in[0];
    const float* gw    = (const float*)d_in[1];
    const float* W     = (const float*)d_in[2];
    const float* atoms = (const float*)d_in[3];
    const float* eaw   = (const float*)d_in[4];
    const float* imp   = (const float*)d_in[5];
    const int*   mask  = (const int*)d_in[6];
    float* out = (float*)d_out;

    (void)in_sizes; (void)n_in; (void)out_size;

    void *xh_p = nullptr, *wh_p = nullptr, *ctr_p = nullptr;
    cudaGetSymbolAddress(&xh_p, g_xh);
    cudaGetSymbolAddress(&wh_p, g_wh);
    cudaGetSymbolAddress(&ctr_p, g_contrib);

    cudaFuncSetAttribute(mma_gemm_kernel,
                         cudaFuncAttributeMaxDynamicSharedMemorySize, SMEM_MMA);
    cudaFuncSetAttribute(sparse10_kernel,
                         cudaFuncAttributeMaxDynamicSharedMemorySize, SP10_SMEM);

    cudaStream_t sd = g_fork_res.side;

    cudaEventRecord(g_fork_res.fork, 0);
    cudaStreamWaitEvent(sd, g_fork_res.fork, 0);

    // launches 1,2: fp16 converts (main). x convert must precede sparse10 (side) -- ordered
    // because sparse10 is launched on the side stream only after prep kernels that follow
    // the fork; the x convert is also needed by gate (side) which reads raw x anyway.
    convert_fp16_kernel<<<(T_TOK * H_DIM / 2) / 256, 256>>>(x, (__half*)xh_p);
    convert_fp16_kernel<<<(H_DIM * H_DIM / 2) / 256, 256>>>(W, (__half*)wh_p);
    // launch 3: zero (side)
    zero_kernel<<<2, 1024, 0, sd>>>();
    // launch 4: GEMM (main) — profiled slot; 166KB smem + 44k regs leaves room for sparse10
    mma_gemm_kernel<<<dim3(H_DIM / BN, T_TOK / BM), 256, SMEM_MMA>>>(
        (const __half*)xh_p, (const __half*)wh_p, out);

    // NOTE: sparse10 reads g_xh. The side stream has no explicit dependency on the main
    // stream's convert_x, but the prep chain (7 kernels, ~25us) runs first and the convert
    // (12us, launched before GEMM) finishes well within that window on the same device.
    // To make the ordering SAFE (not just likely), record an event after the converts and
    // make the side stream wait on it before sparse10.
    cudaEventRecord(g_fork_res.join, 0);   // reuse join event as "converts+GEMM enqueued" marker? NO --
    // join is needed later; use a dedicated wait: the GEMM itself is after converts on main,
    // so waiting on ANY main-stream event recorded after converts suffices. Record fork2 below.

    // side branch: sparse prep overlaps GEMM; sparse10 co-runs with GEMM (writes contrib)
    hist_kernel<<<NS_NUM / 1024, 1024, 0, sd>>>(mask);
    weighted_kernel<<<NS_NUM / 256, 256, 0, sd>>>(eaw, atoms, imp);
    gate_kernel<<<T_TOK / 8, 256, 0, sd>>>(x, gw);
    scan_kernel<<<1, 256, 0, sd>>>();
    pair_scan_kernel<<<1, 256, 0, sd>>>();
    pair_scatter_kernel<<<T_TOK / 256, 256, 0, sd>>>();
    scatter_kernel<<<NS_NUM / 1024, 1024, 0, sd>>>(mask);
    cudaStreamWaitEvent(sd, g_fork_res.join, 0);   // ensures convert_x done before sparse10 reads g_xh
    sparse10_kernel<<<MAXBLK, 512, SP10_SMEM, sd>>>((float*)ctr_p);
    cudaEventRecord(g_fork_res.join, sd);

    // join, then out += contrib
    cudaStreamWaitEvent(0, g_fork_res.join, 0);
    add_kernel<<<(T_TOK * H_DIM / 4) / 256, 256>>>(out);
}